// round 1
// baseline (speedup 1.0000x reference)
#include <cuda_runtime.h>
#include <math.h>

#define BB 2
#define NN 512
#define CD 64
#define PF 128
#define DD 256
#define KNN 16
#define HH 8
#define DH 32
#define QKVD 768
#define CIN 195   // CD+PF+3

// ---------------- scratch (device globals; no allocations allowed) ----------------
__device__ float g_W1t[CIN*DD];
__device__ float g_Wr1t[DD*DD];
__device__ float g_Wr2t[DD*DD];
__device__ float g_Wint[DD*QKVD];
__device__ float g_Wot[DD*DD];
__device__ float g_mu[5];
__device__ float g_G[25];
__device__ float g_local[BB*NN*DD];
__device__ float g_regin[BB*NN*DD];
__device__ float g_combined[BB*NN*DD];
__device__ float g_qkv[BB*NN*QKVD];
__device__ float g_o[BB*NN*DD];
__device__ float g_gfeat[BB*DD];

__device__ __forceinline__ float gelu_exact(float x) {
    return 0.5f * x * (1.0f + erff(x * 0.70710678118654752440f));
}

// ---------------- prep: transpose weights for coalesced k-major access ----------------
__global__ void prep_transpose(const float* __restrict__ W1, const float* __restrict__ Wr1,
                               const float* __restrict__ Wr2, const float* __restrict__ Win,
                               const float* __restrict__ Wo) {
    int i = blockIdx.x * blockDim.x + threadIdx.x;
    int stride = gridDim.x * blockDim.x;
    for (int j = i; j < DD*CIN; j += stride) { int d = j / CIN, k = j % CIN; g_W1t[k*DD + d] = W1[j]; }
    for (int j = i; j < DD*DD; j += stride) {
        int d = j >> 8, k = j & 255;
        g_Wr1t[k*DD + d] = Wr1[j];
        g_Wr2t[k*DD + d] = Wr2[j];
        g_Wot [k*DD + d] = Wo[j];
    }
    for (int j = i; j < QKVD*DD; j += stride) { int d = j >> 8, k = j & 255; g_Wint[k*QKVD + d] = Win[j]; }
}

// ---------------- Gram precompute for spatial LN closed form ----------------
__device__ __forceinline__ float blockSumAll(float v, float* red) {
    #pragma unroll
    for (int o = 16; o > 0; o >>= 1) v += __shfl_down_sync(0xffffffffu, v, o);
    int w = threadIdx.x >> 5, l = threadIdx.x & 31;
    __syncthreads();
    if (l == 0) red[w] = v;
    __syncthreads();
    return red[0]+red[1]+red[2]+red[3]+red[4]+red[5]+red[6]+red[7];
}

__global__ void gram_kernel(const float* __restrict__ Ws, const float* __restrict__ bs) {
    __shared__ float red[8];
    int d = threadIdx.x;
    float4 w4 = *(const float4*)(Ws + d*4);
    float v[5] = {w4.x, w4.y, w4.z, w4.w, bs[d]};
    float mu[5];
    #pragma unroll
    for (int p = 0; p < 5; p++) mu[p] = blockSumAll(v[p], red) * (1.0f/DD);
    #pragma unroll
    for (int p = 0; p < 5; p++) v[p] -= mu[p];
    for (int p = 0; p < 5; p++)
        for (int q = 0; q < 5; q++) {
            float s = blockSumAll(v[p]*v[q], red) * (1.0f/DD);
            if (d == 0) g_G[p*5 + q] = s;
        }
    if (d == 0) { for (int p = 0; p < 5; p++) g_mu[p] = mu[p]; }
}

// ---------------- per-row-tile LayerNorm helper (8 rows, 256 threads) ----------------
__device__ __forceinline__ void ln_rows8(float (*h_sh)[DD], float (*stat)[2]) {
    // caller must __syncthreads() after h_sh writes before calling
    int w = threadIdx.x >> 5, l = threadIdx.x & 31;
    float s = 0.f, s2 = 0.f;
    for (int i = l; i < DD; i += 32) { float v = h_sh[w][i]; s += v; s2 += v*v; }
    #pragma unroll
    for (int o = 16; o > 0; o >>= 1) {
        s  += __shfl_down_sync(0xffffffffu, s,  o);
        s2 += __shfl_down_sync(0xffffffffu, s2, o);
    }
    if (l == 0) {
        float m = s * (1.0f/DD);
        stat[w][0] = m;
        stat[w][1] = rsqrtf(s2 * (1.0f/DD) - m*m + 1e-5f);
    }
    __syncthreads();
}

// ---------------- K1: local = gelu(ln(concat @ W1.T + b1)) ----------------
__global__ void local_encoder_kernel(const float* __restrict__ x, const float* __restrict__ pf,
                                     const float* __restrict__ xyz, const float* __restrict__ b1,
                                     const float* __restrict__ g1, const float* __restrict__ be1) {
    __shared__ float in_sh[8][CIN];
    __shared__ float h_sh[8][DD];
    __shared__ float stat[8][2];
    int row0 = blockIdx.x * 8;
    int tid = threadIdx.x;
    for (int idx = tid; idx < 8*CIN; idx += 256) {
        int r = idx / CIN, k = idx % CIN, row = row0 + r;
        float v;
        if (k < CD)          v = x[row*CD + k];
        else if (k < CD+PF)  v = pf[row*PF + (k - CD)];
        else                 v = xyz[row*3 + (k - CD - PF)];
        in_sh[r][k] = v;
    }
    __syncthreads();
    float acc[8];
    float bbias = b1[tid];
    #pragma unroll
    for (int r = 0; r < 8; r++) acc[r] = bbias;
    for (int k = 0; k < CIN; k++) {
        float w = g_W1t[k*DD + tid];
        #pragma unroll
        for (int r = 0; r < 8; r++) acc[r] = fmaf(in_sh[r][k], w, acc[r]);
    }
    #pragma unroll
    for (int r = 0; r < 8; r++) h_sh[r][tid] = acc[r];
    __syncthreads();
    ln_rows8(h_sh, stat);
    float gv = g1[tid], bev = be1[tid];
    #pragma unroll
    for (int r = 0; r < 8; r++) {
        float t = (h_sh[r][tid] - stat[r][0]) * stat[r][1] * gv + bev;
        g_local[(row0 + r)*DD + tid] = gelu_exact(t);
    }
}

// ---------------- K2: kNN select + gather-mean -> g_regin ----------------
__global__ void knn_region_kernel(const float* __restrict__ xyz) {
    __shared__ float xs[NN*3];
    __shared__ float d2[NN];
    __shared__ int   sel[KNN];
    __shared__ float wv[8];
    __shared__ int   wi[8];
    int b = blockIdx.x >> 9;
    int i = blockIdx.x & 511;
    int tid = threadIdx.x;
    for (int idx = tid; idx < NN*3; idx += 256) xs[idx] = xyz[b*NN*3 + idx];
    __syncthreads();
    float xi = xs[i*3], yi = xs[i*3+1], zi = xs[i*3+2];
    for (int j = tid; j < NN; j += 256) {
        float dx = xi - xs[j*3], dy = yi - xs[j*3+1], dz = zi - xs[j*3+2];
        d2[j] = dx*dx + dy*dy + dz*dz;
    }
    __syncthreads();
    int lane = tid & 31, warp = tid >> 5;
    for (int it = 0; it < KNN; it++) {
        float v = d2[tid]; int bi = tid;
        float v2 = d2[tid + 256];
        if (v2 < v) { v = v2; bi = tid + 256; }
        #pragma unroll
        for (int o = 16; o > 0; o >>= 1) {
            float ov = __shfl_down_sync(0xffffffffu, v, o);
            int   oi = __shfl_down_sync(0xffffffffu, bi, o);
            if (ov < v || (ov == v && oi < bi)) { v = ov; bi = oi; }
        }
        if (lane == 0) { wv[warp] = v; wi[warp] = bi; }
        __syncthreads();
        if (tid == 0) {
            float bv = wv[0]; int bx = wi[0];
            for (int t = 1; t < 8; t++)
                if (wv[t] < bv || (wv[t] == bv && wi[t] < bx)) { bv = wv[t]; bx = wi[t]; }
            sel[it] = bx;
            d2[bx] = 3.4e38f;
        }
        __syncthreads();
    }
    float s = 0.f;
    #pragma unroll
    for (int k = 0; k < KNN; k++) s += g_local[(b*NN + sel[k])*DD + tid];
    g_regin[(b*NN + i)*DD + tid] = s * (1.0f/KNN);
}

// ---------------- K3: gfeat = ln(mean_n(local) @ Wg.T + bg) ----------------
__global__ void gfeat_kernel(const float* __restrict__ Wg, const float* __restrict__ bg,
                             const float* __restrict__ gg, const float* __restrict__ beg) {
    __shared__ float lm[DD];
    __shared__ float red[16];
    int b = blockIdx.x, tid = threadIdx.x;
    float s = 0.f;
    for (int n = 0; n < NN; n++) s += g_local[(b*NN + n)*DD + tid];
    lm[tid] = s * (1.0f/NN);
    __syncthreads();
    float acc = bg[tid];
    for (int k = 0; k < DD; k++) acc = fmaf(lm[k], Wg[tid*DD + k], acc);
    float sv = acc, s2 = acc*acc;
    #pragma unroll
    for (int o = 16; o > 0; o >>= 1) {
        sv += __shfl_down_sync(0xffffffffu, sv, o);
        s2 += __shfl_down_sync(0xffffffffu, s2, o);
    }
    int w = tid >> 5, l = tid & 31;
    if (l == 0) { red[w] = sv; red[8 + w] = s2; }
    __syncthreads();
    float S = 0.f, S2 = 0.f;
    #pragma unroll
    for (int t = 0; t < 8; t++) { S += red[t]; S2 += red[8 + t]; }
    float m = S * (1.0f/DD);
    float is = rsqrtf(S2 * (1.0f/DD) - m*m + 1e-5f);
    g_gfeat[b*DD + tid] = (acc - m) * is * gg[tid] + beg[tid];
}

// ---------------- K4: region MLP (2 GEMMs + 2 LN + GELU) + combined ----------------
__global__ void region_kernel(const float* __restrict__ br1, const float* __restrict__ gr1,
                              const float* __restrict__ ber1, const float* __restrict__ br2,
                              const float* __restrict__ gr2, const float* __restrict__ ber2) {
    __shared__ float in_sh[8][DD];
    __shared__ float h_sh[8][DD];
    __shared__ float stat[8][2];
    int row0 = blockIdx.x * 8;
    int tid = threadIdx.x;
    for (int idx = tid; idx < 8*DD; idx += 256) {
        int r = idx >> 8, k = idx & 255;
        in_sh[r][k] = g_regin[(row0 + r)*DD + k];
    }
    __syncthreads();
    float acc[8];
    float bbias = br1[tid];
    #pragma unroll
    for (int r = 0; r < 8; r++) acc[r] = bbias;
    for (int k = 0; k < DD; k++) {
        float w = g_Wr1t[k*DD + tid];
        #pragma unroll
        for (int r = 0; r < 8; r++) acc[r] = fmaf(in_sh[r][k], w, acc[r]);
    }
    #pragma unroll
    for (int r = 0; r < 8; r++) h_sh[r][tid] = acc[r];
    __syncthreads();
    ln_rows8(h_sh, stat);
    float g1 = gr1[tid], b1v = ber1[tid];
    #pragma unroll
    for (int r = 0; r < 8; r++) {
        float t = (h_sh[r][tid] - stat[r][0]) * stat[r][1] * g1 + b1v;
        in_sh[r][tid] = gelu_exact(t);
    }
    __syncthreads();
    bbias = br2[tid];
    #pragma unroll
    for (int r = 0; r < 8; r++) acc[r] = bbias;
    for (int k = 0; k < DD; k++) {
        float w = g_Wr2t[k*DD + tid];
        #pragma unroll
        for (int r = 0; r < 8; r++) acc[r] = fmaf(in_sh[r][k], w, acc[r]);
    }
    #pragma unroll
    for (int r = 0; r < 8; r++) h_sh[r][tid] = acc[r];
    __syncthreads();
    ln_rows8(h_sh, stat);
    float g2 = gr2[tid], b2v = ber2[tid];
    #pragma unroll
    for (int r = 0; r < 8; r++) {
        int row = row0 + r;
        int b = row >> 9;
        float t = (h_sh[r][tid] - stat[r][0]) * stat[r][1] * g2 + b2v;
        g_combined[row*DD + tid] = g_local[row*DD + tid] + t + g_gfeat[b*DD + tid];
    }
}

// ---------------- K5: QKV projection ----------------
__global__ void qkv_kernel(const float* __restrict__ bin_) {
    __shared__ float in_sh[8][DD];
    int row0 = blockIdx.x * 8;
    int tid = threadIdx.x;
    for (int idx = tid; idx < 8*DD; idx += 256) {
        int r = idx >> 8, k = idx & 255;
        in_sh[r][k] = g_combined[(row0 + r)*DD + k];
    }
    __syncthreads();
    for (int co = 0; co < 3; co++) {
        int ch = co*256 + tid;
        float acc[8];
        float bbias = bin_[ch];
        #pragma unroll
        for (int r = 0; r < 8; r++) acc[r] = bbias;
        for (int k = 0; k < DD; k++) {
            float w = g_Wint[k*QKVD + ch];
            #pragma unroll
            for (int r = 0; r < 8; r++) acc[r] = fmaf(in_sh[r][k], w, acc[r]);
        }
        #pragma unroll
        for (int r = 0; r < 8; r++) g_qkv[(row0 + r)*QKVD + ch] = acc[r];
    }
}

// ---------------- K6: multi-head attention (flash-style, thread-per-query) ----------------
__global__ void attn_kernel() {
    __shared__ float Ksh[128][DH];
    __shared__ float Vsh[128][DH];
    int b = blockIdx.z, h = blockIdx.y;
    int qi = blockIdx.x * 64 + threadIdx.x;
    int tid = threadIdx.x;
    float q[DH];
    const float* qrow = g_qkv + (b*NN + qi)*QKVD + h*DH;
    #pragma unroll
    for (int d4 = 0; d4 < DH; d4 += 4) {
        float4 v = *(const float4*)(qrow + d4);
        q[d4] = v.x; q[d4+1] = v.y; q[d4+2] = v.z; q[d4+3] = v.w;
    }
    float m = -1e30f, l = 0.f, o[DH];
    #pragma unroll
    for (int d = 0; d < DH; d++) o[d] = 0.f;
    const float scale = 0.17677669529663688f;  // 1/sqrt(32)
    for (int jt = 0; jt < NN; jt += 128) {
        __syncthreads();
        for (int idx = tid; idx < 128*DH; idx += 64) {
            int jj = idx >> 5, dd = idx & 31;
            int base = (b*NN + jt + jj)*QKVD + h*DH + dd;
            Ksh[jj][dd] = g_qkv[base + DD];
            Vsh[jj][dd] = g_qkv[base + 2*DD];
        }
        __syncthreads();
        for (int jj = 0; jj < 128; jj++) {
            float s = 0.f;
            #pragma unroll
            for (int d = 0; d < DH; d++) s = fmaf(q[d], Ksh[jj][d], s);
            s *= scale;
            if (s > m) {
                float corr = __expf(m - s);
                l *= corr;
                #pragma unroll
                for (int d = 0; d < DH; d++) o[d] *= corr;
                m = s;
            }
            float p = __expf(s - m);
            l += p;
            #pragma unroll
            for (int d = 0; d < DH; d++) o[d] = fmaf(p, Vsh[jj][d], o[d]);
        }
    }
    float inv = 1.0f / l;
    float* orow = g_o + (b*NN + qi)*DD + h*DH;
    #pragma unroll
    for (int d = 0; d < DH; d++) orow[d] = o[d] * inv;
}

// ---------------- K7: spatial encoding (closed-form LN stats via 5x5 Gram) ----------------
__global__ void spatial_kernel(const float* __restrict__ xyz, const float* __restrict__ Ws,
                               const float* __restrict__ bs, const float* __restrict__ gs,
                               const float* __restrict__ bes, float* __restrict__ out) {
    __shared__ float  xs[NN*3];
    __shared__ float4 cA[NN];  // a, b, c, rd
    __shared__ float2 cB[NN];  // mean, inv_std
    int b = blockIdx.x >> 9, i = blockIdx.x & 511;
    int tid = threadIdx.x;
    for (int idx = tid; idx < NN*3; idx += 256) xs[idx] = xyz[b*NN*3 + idx];
    __syncthreads();
    float xi = xs[i*3], yi = xs[i*3+1], zi = xs[i*3+2];
    for (int j = tid; j < NN; j += 256) {
        float a = xi - xs[j*3], bc = yi - xs[j*3+1], c = zi - xs[j*3+2];
        float rd = sqrtf(a*a + bc*bc + c*c);
        float cf[5] = {a, bc, c, rd, 1.0f};
        float mm = fmaf(a, g_mu[0], fmaf(bc, g_mu[1], fmaf(c, g_mu[2], fmaf(rd, g_mu[3], g_mu[4]))));
        float var = 0.f;
        #pragma unroll
        for (int p = 0; p < 5; p++) {
            float t = 0.f;
            #pragma unroll
            for (int q = 0; q < 5; q++) t = fmaf(g_G[p*5 + q], cf[q], t);
            var = fmaf(cf[p], t, var);
        }
        cA[j] = make_float4(a, bc, c, rd);
        cB[j] = make_float2(mm, rsqrtf(var + 1e-5f));
    }
    __syncthreads();
    float4 wv = *(const float4*)(Ws + tid*4);
    float bsd = bs[tid], gd = gs[tid], bed = bes[tid];
    float acc = 0.f;
    for (int j = 0; j < NN; j++) {
        float4 cc = cA[j];
        float2 ms = cB[j];
        float hh = fmaf(cc.x, wv.x, fmaf(cc.y, wv.y, fmaf(cc.z, wv.z, fmaf(cc.w, wv.w, bsd))));
        float isg = ms.y * gd;
        float off = fmaf(-ms.x, isg, bed);
        float t = fmaf(hh, isg, off);
        acc += gelu_exact(t);
    }
    out[(b*NN + i)*DD + tid] = acc * (1.0f/NN);
}

// ---------------- K8: out += o @ Wo.T + bo ----------------
__global__ void oproj_kernel(const float* __restrict__ bo, float* __restrict__ out) {
    __shared__ float in_sh[8][DD];
    int row0 = blockIdx.x * 8;
    int tid = threadIdx.x;
    for (int idx = tid; idx < 8*DD; idx += 256) {
        int r = idx >> 8, k = idx & 255;
        in_sh[r][k] = g_o[(row0 + r)*DD + k];
    }
    __syncthreads();
    float acc[8];
    float bbias = bo[tid];
    #pragma unroll
    for (int r = 0; r < 8; r++) acc[r] = bbias;
    for (int k = 0; k < DD; k++) {
        float w = g_Wot[k*DD + tid];
        #pragma unroll
        for (int r = 0; r < 8; r++) acc[r] = fmaf(in_sh[r][k], w, acc[r]);
    }
    #pragma unroll
    for (int r = 0; r < 8; r++) {
        int row = row0 + r;
        out[row*DD + tid] += acc[r];
    }
}

// ---------------- launch ----------------
extern "C" void kernel_launch(void* const* d_in, const int* in_sizes, int n_in,
                              void* d_out, int out_size) {
    const float* x    = (const float*)d_in[0];
    const float* pf   = (const float*)d_in[1];
    const float* xyz  = (const float*)d_in[2];
    const float* W1   = (const float*)d_in[3];
    const float* b1   = (const float*)d_in[4];
    const float* g1   = (const float*)d_in[5];
    const float* be1  = (const float*)d_in[6];
    const float* Wr1  = (const float*)d_in[7];
    const float* br1  = (const float*)d_in[8];
    const float* gr1  = (const float*)d_in[9];
    const float* ber1 = (const float*)d_in[10];
    const float* Wr2  = (const float*)d_in[11];
    const float* br2  = (const float*)d_in[12];
    const float* gr2  = (const float*)d_in[13];
    const float* ber2 = (const float*)d_in[14];
    const float* Wg   = (const float*)d_in[15];
    const float* bg   = (const float*)d_in[16];
    const float* gg   = (const float*)d_in[17];
    const float* beg  = (const float*)d_in[18];
    const float* Win  = (const float*)d_in[19];
    const float* bin_ = (const float*)d_in[20];
    const float* Wo   = (const float*)d_in[21];
    const float* bo   = (const float*)d_in[22];
    const float* Ws   = (const float*)d_in[23];
    const float* bs   = (const float*)d_in[24];
    const float* gs   = (const float*)d_in[25];
    const float* bes  = (const float*)d_in[26];
    float* out = (float*)d_out;

    prep_transpose<<<256, 256>>>(W1, Wr1, Wr2, Win, Wo);
    gram_kernel<<<1, 256>>>(Ws, bs);
    local_encoder_kernel<<<128, 256>>>(x, pf, xyz, b1, g1, be1);
    knn_region_kernel<<<BB*NN, 256>>>(xyz);
    gfeat_kernel<<<BB, 256>>>(Wg, bg, gg, beg);
    region_kernel<<<128, 256>>>(br1, gr1, ber1, br2, gr2, ber2);
    qkv_kernel<<<128, 256>>>(bin_);
    dim3 ag(NN/64, HH, BB);
    attn_kernel<<<ag, 64>>>();
    spatial_kernel<<<BB*NN, 256>>>(xyz, Ws, bs, gs, bes, out);
    oproj_kernel<<<128, 256>>>(bo, out);
}

// round 3
// speedup vs baseline: 1.7468x; 1.7468x over previous
#include <cuda_runtime.h>
#include <math.h>

#define BB 2
#define NN 512
#define CD 64
#define PF 128
#define DD 256
#define KNN 16
#define HH 8
#define DH 32
#define QKVD 768
#define CIN 195
#define KQ1 49      // ceil(195/4)
#define KQD 64      // 256/4
#define NSPLIT 4

// ---------------- scratch (device globals) ----------------
__device__ float4 g_W1p[KQ1*DD];     // [kq][d] = W1[d][4kq..4kq+3] (zero-padded)
__device__ float4 g_Wr1p[KQD*DD];
__device__ float4 g_Wr2p[KQD*DD];
__device__ float4 g_Winp[KQD*QKVD];
__device__ float4 g_Wop[KQD*DD];
__device__ float g_mu[5];
__device__ float g_G[25];
__device__ __align__(16) float g_local[BB*NN*DD];
__device__ __align__(16) float g_regin[BB*NN*DD];
__device__ __align__(16) float g_combined[BB*NN*DD];
__device__ __align__(16) float g_qkv[BB*NN*QKVD];
__device__ float g_gfeat[BB*DD];
__device__ float g_pm[BB*NSPLIT*HH*NN];
__device__ float g_pl[BB*NSPLIT*HH*NN];
__device__ __align__(16) float g_po[BB*NSPLIT*HH*NN*DH];

// ---------------- fast exact-GELU: A&S 7.1.26 erf, |eps| <= 1.5e-7 ----------------
__device__ __forceinline__ float rcp_fast(float x) {
    float r;
    asm("rcp.approx.ftz.f32 %0, %1;" : "=f"(r) : "f"(x));
    return r;
}
__device__ __forceinline__ float gelu_fast(float x) {
    float xs = x * 0.70710678118654752440f;
    float ax = fabsf(xs);
    float t  = rcp_fast(fmaf(0.3275911f, ax, 1.0f));
    float p  = t * fmaf(t, fmaf(t, fmaf(t, fmaf(t, 1.061405429f, -1.453152027f),
                       1.421413741f), -0.284496736f), 0.254829592f);
    float e  = __expf(-xs * xs);
    float erfv = fmaf(-p, e, 1.0f);           // erf(|xs|)
    erfv = copysignf(erfv, xs);
    return 0.5f * x * (1.0f + erfv);
}

// ---------------- K0: weight packing + 5x5 Gram (fused) ----------------
__device__ __forceinline__ float blockSumAll(float v, float* red) {
    #pragma unroll
    for (int o = 16; o > 0; o >>= 1) v += __shfl_down_sync(0xffffffffu, v, o);
    int w = threadIdx.x >> 5, l = threadIdx.x & 31;
    __syncthreads();
    if (l == 0) red[w] = v;
    __syncthreads();
    return red[0]+red[1]+red[2]+red[3]+red[4]+red[5]+red[6]+red[7];
}

#define NPREP 64
__global__ void prep_gram_kernel(const float* __restrict__ W1, const float* __restrict__ Wr1,
                                 const float* __restrict__ Wr2, const float* __restrict__ Win,
                                 const float* __restrict__ Wo, const float* __restrict__ Ws,
                                 const float* __restrict__ bs) {
    if (blockIdx.x < NPREP) {
        int i = blockIdx.x * 256 + threadIdx.x;
        int stride = NPREP * 256;
        for (int e = i; e < KQ1*DD; e += stride) {
            int kq = e / DD, d = e % DD;
            float4 v;
            int k = kq * 4;
            v.x = (k+0 < CIN) ? W1[d*CIN + k+0] : 0.f;
            v.y = (k+1 < CIN) ? W1[d*CIN + k+1] : 0.f;
            v.z = (k+2 < CIN) ? W1[d*CIN + k+2] : 0.f;
            v.w = (k+3 < CIN) ? W1[d*CIN + k+3] : 0.f;
            g_W1p[e] = v;
        }
        for (int e = i; e < KQD*DD; e += stride) {
            int kq = e >> 8, d = e & 255;
            int k = kq * 4;
            g_Wr1p[e] = make_float4(Wr1[d*DD+k], Wr1[d*DD+k+1], Wr1[d*DD+k+2], Wr1[d*DD+k+3]);
            g_Wr2p[e] = make_float4(Wr2[d*DD+k], Wr2[d*DD+k+1], Wr2[d*DD+k+2], Wr2[d*DD+k+3]);
            g_Wop[e]  = make_float4(Wo[d*DD+k],  Wo[d*DD+k+1],  Wo[d*DD+k+2],  Wo[d*DD+k+3]);
        }
        for (int e = i; e < KQD*QKVD; e += stride) {
            int kq = e / QKVD, ch = e % QKVD;
            int k = kq * 4;
            g_Winp[e] = make_float4(Win[ch*DD+k], Win[ch*DD+k+1], Win[ch*DD+k+2], Win[ch*DD+k+3]);
        }
    } else {
        // Gram block
        __shared__ float red[8];
        int d = threadIdx.x;
        float4 w4 = *(const float4*)(Ws + d*4);
        float v[5] = {w4.x, w4.y, w4.z, w4.w, bs[d]};
        float mu[5];
        #pragma unroll
        for (int p = 0; p < 5; p++) mu[p] = blockSumAll(v[p], red) * (1.0f/DD);
        #pragma unroll
        for (int p = 0; p < 5; p++) v[p] -= mu[p];
        for (int p = 0; p < 5; p++)
            for (int q = 0; q < 5; q++) {
                float s = blockSumAll(v[p]*v[q], red) * (1.0f/DD);
                if (d == 0) g_G[p*5 + q] = s;
            }
        if (d == 0) { for (int p = 0; p < 5; p++) g_mu[p] = mu[p]; }
    }
}

// ---------------- LN helper (8 rows, 256 threads) ----------------
__device__ __forceinline__ void ln_rows8(float (*h_sh)[DD], float (*stat)[2]) {
    int w = threadIdx.x >> 5, l = threadIdx.x & 31;
    float s = 0.f, s2 = 0.f;
    for (int i = l; i < DD; i += 32) { float v = h_sh[w][i]; s += v; s2 += v*v; }
    #pragma unroll
    for (int o = 16; o > 0; o >>= 1) {
        s  += __shfl_down_sync(0xffffffffu, s,  o);
        s2 += __shfl_down_sync(0xffffffffu, s2, o);
    }
    if (l == 0) {
        float m = s * (1.0f/DD);
        stat[w][0] = m;
        stat[w][1] = rsqrtf(s2 * (1.0f/DD) - m*m + 1e-5f);
    }
    __syncthreads();
}

// ---------------- K1: local = gelu(ln(concat @ W1.T + b1)) ----------------
__global__ void local_encoder_kernel(const float* __restrict__ x, const float* __restrict__ pf,
                                     const float* __restrict__ xyz, const float* __restrict__ b1,
                                     const float* __restrict__ g1, const float* __restrict__ be1) {
    __shared__ __align__(16) float in_sh[8][196];
    __shared__ float h_sh[8][DD];
    __shared__ float stat[8][2];
    int row0 = blockIdx.x * 8;
    int tid = threadIdx.x;
    for (int idx = tid; idx < 8*196; idx += 256) {
        int r = idx / 196, k = idx % 196, row = row0 + r;
        float v;
        if (k < CD)          v = x[row*CD + k];
        else if (k < CD+PF)  v = pf[row*PF + (k - CD)];
        else if (k < CIN)    v = xyz[row*3 + (k - CD - PF)];
        else                 v = 0.f;
        in_sh[r][k] = v;
    }
    __syncthreads();
    float acc[8];
    float bbias = b1[tid];
    #pragma unroll
    for (int r = 0; r < 8; r++) acc[r] = bbias;
    for (int kq = 0; kq < KQ1; kq++) {
        float4 w = g_W1p[kq*DD + tid];
        #pragma unroll
        for (int r = 0; r < 8; r++) {
            float4 iv = ((const float4*)in_sh[r])[kq];
            acc[r] = fmaf(iv.x, w.x, acc[r]);
            acc[r] = fmaf(iv.y, w.y, acc[r]);
            acc[r] = fmaf(iv.z, w.z, acc[r]);
            acc[r] = fmaf(iv.w, w.w, acc[r]);
        }
    }
    #pragma unroll
    for (int r = 0; r < 8; r++) h_sh[r][tid] = acc[r];
    __syncthreads();
    ln_rows8(h_sh, stat);
    float gv = g1[tid], bev = be1[tid];
    #pragma unroll
    for (int r = 0; r < 8; r++) {
        float t = (h_sh[r][tid] - stat[r][0]) * stat[r][1] * gv + bev;
        g_local[(row0 + r)*DD + tid] = gelu_fast(t);
    }
}

// ---------------- K2: fused kNN + gather-mean + spatial encoding ----------------
__global__ void knn_spatial_kernel(const float* __restrict__ xyz, const float* __restrict__ Ws,
                                   const float* __restrict__ bs, const float* __restrict__ gs,
                                   const float* __restrict__ bes, float* __restrict__ out) {
    __shared__ float  xs[NN*3];
    __shared__ float  d2s[NN];
    __shared__ float4 cA[NN];   // rel (a,b,c) + rd
    __shared__ float2 cB[NN];   // (inv_std, mean*inv_std)
    __shared__ int    sel[KNN];
    __shared__ float  rv[8];
    __shared__ int    ri[8];
    int b = blockIdx.x >> 9, i = blockIdx.x & 511;
    int tid = threadIdx.x;
    for (int idx = tid; idx < NN*3; idx += 256) xs[idx] = xyz[b*NN*3 + idx];
    __syncthreads();
    float xi = xs[i*3], yi = xs[i*3+1], zi = xs[i*3+2];
    for (int j = tid; j < NN; j += 256) {
        float a = xi - xs[j*3], bc = yi - xs[j*3+1], c = zi - xs[j*3+2];
        float d2 = a*a + bc*bc + c*c;
        float rd = sqrtf(d2);
        d2s[j] = d2;
        float cf[5] = {a, bc, c, rd, 1.0f};
        float mm = fmaf(a, g_mu[0], fmaf(bc, g_mu[1], fmaf(c, g_mu[2], fmaf(rd, g_mu[3], g_mu[4]))));
        float var = 0.f;
        #pragma unroll
        for (int p = 0; p < 5; p++) {
            float t = 0.f;
            #pragma unroll
            for (int q = 0; q < 5; q++) t = fmaf(g_G[p*5 + q], cf[q], t);
            var = fmaf(cf[p], t, var);
        }
        float is = rsqrtf(var + 1e-5f);
        cA[j] = make_float4(a, bc, c, rd);
        cB[j] = make_float2(is, mm * is);
    }
    __syncthreads();
    // --- kNN selection: 16 rounds of block argmin (lowest-index tiebreak) ---
    int lane = tid & 31, warp = tid >> 5;
    for (int it = 0; it < KNN; it++) {
        float v = d2s[tid]; int bi = tid;
        float v2 = d2s[tid + 256];
        if (v2 < v) { v = v2; bi = tid + 256; }
        #pragma unroll
        for (int o = 16; o > 0; o >>= 1) {
            float ov = __shfl_down_sync(0xffffffffu, v, o);
            int   oi = __shfl_down_sync(0xffffffffu, bi, o);
            if (ov < v || (ov == v && oi < bi)) { v = ov; bi = oi; }
        }
        if (lane == 0) { rv[warp] = v; ri[warp] = bi; }
        __syncthreads();
        if (tid == 0) {
            float bv = rv[0]; int bx = ri[0];
            for (int t = 1; t < 8; t++)
                if (rv[t] < bv || (rv[t] == bv && ri[t] < bx)) { bv = rv[t]; bx = ri[t]; }
            sel[it] = bx;
            d2s[bx] = 3.4e38f;
        }
        __syncthreads();
    }
    // --- gather mean over K neighbors ---
    float sg = 0.f;
    #pragma unroll
    for (int k = 0; k < KNN; k++) sg += g_local[(b*NN + sel[k])*DD + tid];
    g_regin[(b*NN + i)*DD + tid] = sg * (1.0f/KNN);
    // --- spatial: mean_j gelu(ln(concat(rel,rd) @ Ws.T + bs)) via closed-form stats ---
    float4 wv4 = *(const float4*)(Ws + tid*4);
    float bsd = bs[tid], gd = gs[tid], bed = bes[tid];
    float acc = 0.f;
    #pragma unroll 4
    for (int j = 0; j < NN; j++) {
        float4 cc = cA[j];
        float2 sb = cB[j];
        float hh = fmaf(cc.x, wv4.x, fmaf(cc.y, wv4.y, fmaf(cc.z, wv4.z, fmaf(cc.w, wv4.w, bsd))));
        float isg = sb.x * gd;
        float off = fmaf(-sb.y, gd, bed);
        acc += gelu_fast(fmaf(hh, isg, off));
    }
    out[(b*NN + i)*DD + tid] = acc * (1.0f/NN);
}

// ---------------- K3: gfeat = ln(mean_n(local) @ Wg.T + bg) ----------------
__global__ void gfeat_kernel(const float* __restrict__ Wg, const float* __restrict__ bg,
                             const float* __restrict__ gg, const float* __restrict__ beg) {
    __shared__ float lm[DD];
    __shared__ float red[16];
    int b = blockIdx.x, tid = threadIdx.x;
    float s = 0.f;
    for (int n = 0; n < NN; n++) s += g_local[(b*NN + n)*DD + tid];
    lm[tid] = s * (1.0f/NN);
    __syncthreads();
    float acc = bg[tid];
    for (int k = 0; k < DD; k++) acc = fmaf(lm[k], Wg[tid*DD + k], acc);
    float sv = acc, s2 = acc*acc;
    #pragma unroll
    for (int o = 16; o > 0; o >>= 1) {
        sv += __shfl_down_sync(0xffffffffu, sv, o);
        s2 += __shfl_down_sync(0xffffffffu, s2, o);
    }
    int w = tid >> 5, l = tid & 31;
    if (l == 0) { red[w] = sv; red[8 + w] = s2; }
    __syncthreads();
    float S = 0.f, S2 = 0.f;
    #pragma unroll
    for (int t = 0; t < 8; t++) { S += red[t]; S2 += red[8 + t]; }
    float m = S * (1.0f/DD);
    float is = rsqrtf(S2 * (1.0f/DD) - m*m + 1e-5f);
    g_gfeat[b*DD + tid] = (acc - m) * is * gg[tid] + beg[tid];
}

// ---------------- K4: region MLP + combined ----------------
__global__ void region_kernel(const float* __restrict__ br1, const float* __restrict__ gr1,
                              const float* __restrict__ ber1, const float* __restrict__ br2,
                              const float* __restrict__ gr2, const float* __restrict__ ber2) {
    __shared__ __align__(16) float in_sh[8][DD];
    __shared__ float h_sh[8][DD];
    __shared__ float stat[8][2];
    int row0 = blockIdx.x * 8;
    int tid = threadIdx.x;
    for (int idx = tid; idx < 8*DD; idx += 256) {
        int r = idx >> 8, k = idx & 255;
        in_sh[r][k] = g_regin[(row0 + r)*DD + k];
    }
    __syncthreads();
    float acc[8];
    float bbias = br1[tid];
    #pragma unroll
    for (int r = 0; r < 8; r++) acc[r] = bbias;
    for (int kq = 0; kq < KQD; kq++) {
        float4 w = g_Wr1p[kq*DD + tid];
        #pragma unroll
        for (int r = 0; r < 8; r++) {
            float4 iv = ((const float4*)in_sh[r])[kq];
            acc[r] = fmaf(iv.x, w.x, acc[r]);
            acc[r] = fmaf(iv.y, w.y, acc[r]);
            acc[r] = fmaf(iv.z, w.z, acc[r]);
            acc[r] = fmaf(iv.w, w.w, acc[r]);
        }
    }
    #pragma unroll
    for (int r = 0; r < 8; r++) h_sh[r][tid] = acc[r];
    __syncthreads();
    ln_rows8(h_sh, stat);
    float g1 = gr1[tid], b1v = ber1[tid];
    #pragma unroll
    for (int r = 0; r < 8; r++) {
        float t = (h_sh[r][tid] - stat[r][0]) * stat[r][1] * g1 + b1v;
        in_sh[r][tid] = gelu_fast(t);
    }
    __syncthreads();
    bbias = br2[tid];
    #pragma unroll
    for (int r = 0; r < 8; r++) acc[r] = bbias;
    for (int kq = 0; kq < KQD; kq++) {
        float4 w = g_Wr2p[kq*DD + tid];
        #pragma unroll
        for (int r = 0; r < 8; r++) {
            float4 iv = ((const float4*)in_sh[r])[kq];
            acc[r] = fmaf(iv.x, w.x, acc[r]);
            acc[r] = fmaf(iv.y, w.y, acc[r]);
            acc[r] = fmaf(iv.z, w.z, acc[r]);
            acc[r] = fmaf(iv.w, w.w, acc[r]);
        }
    }
    __syncthreads();
    #pragma unroll
    for (int r = 0; r < 8; r++) h_sh[r][tid] = acc[r];
    __syncthreads();
    ln_rows8(h_sh, stat);
    float g2 = gr2[tid], b2v = ber2[tid];
    #pragma unroll
    for (int r = 0; r < 8; r++) {
        int row = row0 + r;
        int b = row >> 9;
        float t = (h_sh[r][tid] - stat[r][0]) * stat[r][1] * g2 + b2v;
        g_combined[row*DD + tid] = g_local[row*DD + tid] + t + g_gfeat[b*DD + tid];
    }
}

// ---------------- K5: QKV projection ----------------
__global__ void qkv_kernel(const float* __restrict__ bin_) {
    __shared__ __align__(16) float in_sh[8][DD];
    int row0 = blockIdx.x * 8;
    int tid = threadIdx.x;
    for (int idx = tid; idx < 8*DD; idx += 256) {
        int r = idx >> 8, k = idx & 255;
        in_sh[r][k] = g_combined[(row0 + r)*DD + k];
    }
    __syncthreads();
    float acc[3][8];
    #pragma unroll
    for (int co = 0; co < 3; co++) {
        float bb = bin_[co*256 + tid];
        #pragma unroll
        for (int r = 0; r < 8; r++) acc[co][r] = bb;
    }
    for (int kq = 0; kq < KQD; kq++) {
        float4 iv[8];
        #pragma unroll
        for (int r = 0; r < 8; r++) iv[r] = ((const float4*)in_sh[r])[kq];
        #pragma unroll
        for (int co = 0; co < 3; co++) {
            float4 w = g_Winp[kq*QKVD + co*256 + tid];
            #pragma unroll
            for (int r = 0; r < 8; r++) {
                acc[co][r] = fmaf(iv[r].x, w.x, acc[co][r]);
                acc[co][r] = fmaf(iv[r].y, w.y, acc[co][r]);
                acc[co][r] = fmaf(iv[r].z, w.z, acc[co][r]);
                acc[co][r] = fmaf(iv[r].w, w.w, acc[co][r]);
            }
        }
    }
    #pragma unroll
    for (int co = 0; co < 3; co++)
        #pragma unroll
        for (int r = 0; r < 8; r++)
            g_qkv[(row0 + r)*QKVD + co*256 + tid] = acc[co][r];
}

// ---------------- K6: attention with split-KV (4 splits of 128 keys) ----------------
__global__ void attn_kernel() {
    __shared__ float Ksh[128][DH];
    __shared__ float Vsh[128][DH];
    int z = blockIdx.z;
    int b = z >> 2, s = z & 3;
    int h = blockIdx.y;
    int qi = blockIdx.x * 64 + threadIdx.x;
    int tid = threadIdx.x;
    const float scale = 0.17677669529663688f;  // 1/sqrt(32)
    float q[DH];
    const float* qrow = g_qkv + (b*NN + qi)*QKVD + h*DH;
    #pragma unroll
    for (int d4 = 0; d4 < DH; d4 += 4) {
        float4 v = *(const float4*)(qrow + d4);
        q[d4] = v.x*scale; q[d4+1] = v.y*scale; q[d4+2] = v.z*scale; q[d4+3] = v.w*scale;
    }
    int jt = s * 128;
    for (int idx = tid; idx < 128*DH; idx += 64) {
        int jj = idx >> 5, dd = idx & 31;
        int base = (b*NN + jt + jj)*QKVD + h*DH + dd;
        Ksh[jj][dd] = g_qkv[base + DD];
        Vsh[jj][dd] = g_qkv[base + 2*DD];
    }
    __syncthreads();
    float m = -1e30f, l = 0.f, o[DH];
    #pragma unroll
    for (int d = 0; d < DH; d++) o[d] = 0.f;
    for (int jj = 0; jj < 128; jj++) {
        float s0 = 0.f, s1 = 0.f, s2 = 0.f, s3 = 0.f;
        #pragma unroll
        for (int d = 0; d < DH; d += 4) {
            s0 = fmaf(q[d],   Ksh[jj][d],   s0);
            s1 = fmaf(q[d+1], Ksh[jj][d+1], s1);
            s2 = fmaf(q[d+2], Ksh[jj][d+2], s2);
            s3 = fmaf(q[d+3], Ksh[jj][d+3], s3);
        }
        float sc = (s0 + s1) + (s2 + s3);
        if (sc > m) {
            float corr = __expf(m - sc);
            l *= corr;
            #pragma unroll
            for (int d = 0; d < DH; d++) o[d] *= corr;
            m = sc;
        }
        float p = __expf(sc - m);
        l += p;
        #pragma unroll
        for (int d = 0; d < DH; d++) o[d] = fmaf(p, Vsh[jj][d], o[d]);
    }
    int pb = ((b*NSPLIT + s)*HH + h)*NN + qi;
    g_pm[pb] = m;
    g_pl[pb] = l;
    float* po = g_po + pb*DH;
    #pragma unroll
    for (int d = 0; d < DH; d++) po[d] = o[d];
}

// ---------------- K7: merge attention splits + out += o @ Wo.T + bo ----------------
__global__ void oproj_kernel(const float* __restrict__ bo, float* __restrict__ out) {
    __shared__ float esc[8][HH][NSPLIT];   // e^{m_s-m*}/l* per (row,head,split)
    __shared__ __align__(16) float in_sh[8][DD];
    int row0 = blockIdx.x * 8;
    int b = row0 >> 9;
    int q0 = row0 & 511;              // per-batch query base (BUG FIX: was row0)
    int tid = threadIdx.x;
    if (tid < 64) {
        int r = tid >> 3, h = tid & 7;
        int q = q0 + r;
        float ms[NSPLIT];
        float mx = -1e30f;
        #pragma unroll
        for (int s = 0; s < NSPLIT; s++) {
            ms[s] = g_pm[((b*NSPLIT + s)*HH + h)*NN + q];
            mx = fmaxf(mx, ms[s]);
        }
        float lsum = 0.f;
        #pragma unroll
        for (int s = 0; s < NSPLIT; s++)
            lsum += g_pl[((b*NSPLIT + s)*HH + h)*NN + q] * __expf(ms[s] - mx);
        float inv = 1.0f / lsum;
        #pragma unroll
        for (int s = 0; s < NSPLIT; s++)
            esc[r][h][s] = __expf(ms[s] - mx) * inv;
    }
    __syncthreads();
    int h = tid >> 5, dh = tid & 31;
    #pragma unroll
    for (int r = 0; r < 8; r++) {
        float o = 0.f;
        #pragma unroll
        for (int s = 0; s < NSPLIT; s++)
            o = fmaf(g_po[(((b*NSPLIT + s)*HH + h)*NN + q0 + r)*DH + dh], esc[r][h][s], o);
        in_sh[r][tid] = o;
    }
    __syncthreads();
    float acc[8];
    float bbias = bo[tid];
    #pragma unroll
    for (int r = 0; r < 8; r++) acc[r] = bbias;
    for (int kq = 0; kq < KQD; kq++) {
        float4 w = g_Wop[kq*DD + tid];
        #pragma unroll
        for (int r = 0; r < 8; r++) {
            float4 iv = ((const float4*)in_sh[r])[kq];
            acc[r] = fmaf(iv.x, w.x, acc[r]);
            acc[r] = fmaf(iv.y, w.y, acc[r]);
            acc[r] = fmaf(iv.z, w.z, acc[r]);
            acc[r] = fmaf(iv.w, w.w, acc[r]);
        }
    }
    #pragma unroll
    for (int r = 0; r < 8; r++)
        out[(row0 + r)*DD + tid] += acc[r];
}

// ---------------- launch ----------------
extern "C" void kernel_launch(void* const* d_in, const int* in_sizes, int n_in,
                              void* d_out, int out_size) {
    const float* x    = (const float*)d_in[0];
    const float* pf   = (const float*)d_in[1];
    const float* xyz  = (const float*)d_in[2];
    const float* W1   = (const float*)d_in[3];
    const float* b1   = (const float*)d_in[4];
    const float* g1   = (const float*)d_in[5];
    const float* be1  = (const float*)d_in[6];
    const float* Wr1  = (const float*)d_in[7];
    const float* br1  = (const float*)d_in[8];
    const float* gr1  = (const float*)d_in[9];
    const float* ber1 = (const float*)d_in[10];
    const float* Wr2  = (const float*)d_in[11];
    const float* br2  = (const float*)d_in[12];
    const float* gr2  = (const float*)d_in[13];
    const float* ber2 = (const float*)d_in[14];
    const float* Wg   = (const float*)d_in[15];
    const float* bg   = (const float*)d_in[16];
    const float* gg   = (const float*)d_in[17];
    const float* beg  = (const float*)d_in[18];
    const float* Win  = (const float*)d_in[19];
    const float* bin_ = (const float*)d_in[20];
    const float* Wo   = (const float*)d_in[21];
    const float* bo   = (const float*)d_in[22];
    const float* Ws   = (const float*)d_in[23];
    const float* bs   = (const float*)d_in[24];
    const float* gs   = (const float*)d_in[25];
    const float* bes  = (const float*)d_in[26];
    float* out = (float*)d_out;

    prep_gram_kernel<<<NPREP + 1, 256>>>(W1, Wr1, Wr2, Win, Wo, Ws, bs);
    local_encoder_kernel<<<128, 256>>>(x, pf, xyz, b1, g1, be1);
    knn_spatial_kernel<<<BB*NN, 256>>>(xyz, Ws, bs, gs, bes, out);
    gfeat_kernel<<<BB, 256>>>(Wg, bg, gg, beg);
    region_kernel<<<128, 256>>>(br1, gr1, ber1, br2, gr2, ber2);
    qkv_kernel<<<128, 256>>>(bin_);
    dim3 ag(NN/64, HH, BB*NSPLIT);
    attn_kernel<<<ag, 64>>>();
    oproj_kernel<<<128, 256>>>(bo, out);
}

// round 4
// speedup vs baseline: 2.1446x; 1.2277x over previous
#include <cuda_runtime.h>
#include <math.h>

#define BB 2
#define NN 512
#define CD 64
#define PF 128
#define DD 256
#define KNN 16
#define HH 8
#define DH 32
#define QKVD 768
#define CIN 195
#define KQ1 49      // ceil(195/4)
#define KQD 64      // 256/4
#define NSPLIT 4

typedef unsigned long long ull;

// ---------------- scratch (device globals) ----------------
__device__ float4 g_W1p[KQ1*DD];
__device__ float4 g_Wr1p[KQD*DD];
__device__ float4 g_Wr2p[KQD*DD];
__device__ float4 g_Winp[KQD*QKVD];
__device__ float4 g_Wop[KQD*DD];
__device__ float4 g_Wgp[KQD*DD];
__device__ float g_mu[5];
__device__ float g_G[25];
__device__ __align__(16) float g_local[BB*NN*DD];
__device__ __align__(16) float g_regin[BB*NN*DD];
__device__ __align__(16) float g_qkv[BB*NN*QKVD];
__device__ float g_part[128*DD];          // per-block column partial sums of local
__device__ float g_gfeat[BB*DD];
__device__ float g_pm[BB*NSPLIT*HH*NN];
__device__ float g_pl[BB*NSPLIT*HH*NN];
__device__ __align__(16) float g_po[BB*NSPLIT*HH*NN*DH];

// ---------------- f32x2 packed math (Blackwell FFMA2 path) ----------------
__device__ __forceinline__ ull f2fma(ull a, ull b, ull c){ ull d; asm("fma.rn.f32x2 %0, %1, %2, %3;" : "=l"(d) : "l"(a), "l"(b), "l"(c)); return d; }
__device__ __forceinline__ ull f2mul(ull a, ull b){ ull d; asm("mul.rn.f32x2 %0, %1, %2;" : "=l"(d) : "l"(a), "l"(b)); return d; }
__device__ __forceinline__ ull f2add(ull a, ull b){ ull d; asm("add.rn.f32x2 %0, %1, %2;" : "=l"(d) : "l"(a), "l"(b)); return d; }
__device__ __forceinline__ ull pk2(float lo, float hi){ ull r; asm("mov.b64 %0, {%1,%2};" : "=l"(r) : "f"(lo), "f"(hi)); return r; }
__device__ __forceinline__ float2 up2(ull v){ float2 r; asm("mov.b64 {%0,%1}, %2;" : "=f"(r.x), "=f"(r.y) : "l"(v)); return r; }
__device__ __forceinline__ float rcp_fast(float x){ float r; asm("rcp.approx.ftz.f32 %0, %1;" : "=f"(r) : "f"(x)); return r; }
__device__ __forceinline__ float ex2_fast(float x){ float r; asm("ex2.approx.ftz.f32 %0, %1;" : "=f"(r) : "f"(x)); return r; }

// scalar fast exact-GELU (A&S 7.1.26 erf, |eps|<=1.5e-7)
__device__ __forceinline__ float gelu_fast(float x) {
    float xs = x * 0.70710678118654752440f;
    float ax = fabsf(xs);
    float t  = rcp_fast(fmaf(0.3275911f, ax, 1.0f));
    float p  = t * fmaf(t, fmaf(t, fmaf(t, fmaf(t, 1.061405429f, -1.453152027f),
                       1.421413741f), -0.284496736f), 0.254829592f);
    float e  = ex2_fast(-xs * xs * 1.4426950408889634f);
    float erfv = fmaf(-p, e, 1.0f);
    erfv = copysignf(erfv, xs);
    return 0.5f * x * (1.0f + erfv);
}

// ---------------- K0: weight packing (coalesced reads) + 5x5 Gram ----------------
__device__ __forceinline__ float blockSumAll(float v, float* red) {
    #pragma unroll
    for (int o = 16; o > 0; o >>= 1) v += __shfl_down_sync(0xffffffffu, v, o);
    int w = threadIdx.x >> 5, l = threadIdx.x & 31;
    __syncthreads();
    if (l == 0) red[w] = v;
    __syncthreads();
    return red[0]+red[1]+red[2]+red[3]+red[4]+red[5]+red[6]+red[7];
}

#define NPREP 64
__global__ void prep_gram_kernel(const float* __restrict__ W1, const float* __restrict__ Wr1,
                                 const float* __restrict__ Wr2, const float* __restrict__ Win,
                                 const float* __restrict__ Wo, const float* __restrict__ Wg,
                                 const float* __restrict__ Ws, const float* __restrict__ bs) {
    if (blockIdx.x < NPREP) {
        int i = blockIdx.x * 256 + threadIdx.x;
        int stride = NPREP * 256;
        // W1: scalar reads (row length 195 not 16B-aligned), kq-fastest for coalescing
        for (int e = i; e < DD*KQ1; e += stride) {
            int d = e / KQ1, kq = e % KQ1;
            int k = kq * 4;
            float4 v;
            v.x = (k+0 < CIN) ? W1[d*CIN + k+0] : 0.f;
            v.y = (k+1 < CIN) ? W1[d*CIN + k+1] : 0.f;
            v.z = (k+2 < CIN) ? W1[d*CIN + k+2] : 0.f;
            v.w = (k+3 < CIN) ? W1[d*CIN + k+3] : 0.f;
            g_W1p[kq*DD + d] = v;
        }
        // DD x DD matrices: coalesced float4 reads, scattered stores
        for (int e = i; e < DD*KQD; e += stride) {
            int d = e >> 6, kq = e & 63;
            g_Wr1p[kq*DD + d] = ((const float4*)(Wr1 + d*DD))[kq];
            g_Wr2p[kq*DD + d] = ((const float4*)(Wr2 + d*DD))[kq];
            g_Wop [kq*DD + d] = ((const float4*)(Wo  + d*DD))[kq];
            g_Wgp [kq*DD + d] = ((const float4*)(Wg  + d*DD))[kq];
        }
        for (int e = i; e < QKVD*KQD; e += stride) {
            int ch = e >> 6, kq = e & 63;
            g_Winp[kq*QKVD + ch] = ((const float4*)(Win + ch*DD))[kq];
        }
    } else {
        __shared__ float red[8];
        int d = threadIdx.x;
        float4 w4 = *(const float4*)(Ws + d*4);
        float v[5] = {w4.x, w4.y, w4.z, w4.w, bs[d]};
        float mu[5];
        #pragma unroll
        for (int p = 0; p < 5; p++) mu[p] = blockSumAll(v[p], red) * (1.0f/DD);
        #pragma unroll
        for (int p = 0; p < 5; p++) v[p] -= mu[p];
        for (int p = 0; p < 5; p++)
            for (int q = 0; q < 5; q++) {
                float s = blockSumAll(v[p]*v[q], red) * (1.0f/DD);
                if (d == 0) g_G[p*5 + q] = s;
            }
        if (d == 0) { for (int p = 0; p < 5; p++) g_mu[p] = mu[p]; }
    }
}

// ---------------- LN helper (8 rows, 256 threads) ----------------
__device__ __forceinline__ void ln_rows8(float (*h_sh)[DD], float (*stat)[2]) {
    int w = threadIdx.x >> 5, l = threadIdx.x & 31;
    float s = 0.f, s2 = 0.f;
    for (int i = l; i < DD; i += 32) { float v = h_sh[w][i]; s += v; s2 += v*v; }
    #pragma unroll
    for (int o = 16; o > 0; o >>= 1) {
        s  += __shfl_down_sync(0xffffffffu, s,  o);
        s2 += __shfl_down_sync(0xffffffffu, s2, o);
    }
    if (l == 0) {
        float m = s * (1.0f/DD);
        stat[w][0] = m;
        stat[w][1] = rsqrtf(s2 * (1.0f/DD) - m*m + 1e-5f);
    }
    __syncthreads();
}

// ---------------- K1: local encoder (+ column partial sums for gfeat) ----------------
__global__ void local_encoder_kernel(const float* __restrict__ x, const float* __restrict__ pf,
                                     const float* __restrict__ xyz, const float* __restrict__ b1,
                                     const float* __restrict__ g1, const float* __restrict__ be1) {
    __shared__ __align__(16) float in_sh[8][196];
    __shared__ float h_sh[8][DD];
    __shared__ float stat[8][2];
    int row0 = blockIdx.x * 8;
    int tid = threadIdx.x;
    for (int idx = tid; idx < 8*196; idx += 256) {
        int r = idx / 196, k = idx % 196, row = row0 + r;
        float v;
        if (k < CD)          v = x[row*CD + k];
        else if (k < CD+PF)  v = pf[row*PF + (k - CD)];
        else if (k < CIN)    v = xyz[row*3 + (k - CD - PF)];
        else                 v = 0.f;
        in_sh[r][k] = v;
    }
    __syncthreads();
    float acc[8];
    float bbias = b1[tid];
    #pragma unroll
    for (int r = 0; r < 8; r++) acc[r] = bbias;
    for (int kq = 0; kq < KQ1; kq++) {
        float4 w = g_W1p[kq*DD + tid];
        #pragma unroll
        for (int r = 0; r < 8; r++) {
            float4 iv = ((const float4*)in_sh[r])[kq];
            acc[r] = fmaf(iv.x, w.x, acc[r]);
            acc[r] = fmaf(iv.y, w.y, acc[r]);
            acc[r] = fmaf(iv.z, w.z, acc[r]);
            acc[r] = fmaf(iv.w, w.w, acc[r]);
        }
    }
    #pragma unroll
    for (int r = 0; r < 8; r++) h_sh[r][tid] = acc[r];
    __syncthreads();
    ln_rows8(h_sh, stat);
    float gv = g1[tid], bev = be1[tid];
    float psum = 0.f;
    #pragma unroll
    for (int r = 0; r < 8; r++) {
        float t = (h_sh[r][tid] - stat[r][0]) * stat[r][1] * gv + bev;
        float g = gelu_fast(t);
        psum += g;
        g_local[(row0 + r)*DD + tid] = g;
    }
    g_part[blockIdx.x*DD + tid] = psum;
}

// ---------------- K2: fused kNN + gather-mean + spatial (f32x2 packed) ----------------
__global__ void knn_spatial_kernel(const float* __restrict__ xyz, const float* __restrict__ Ws,
                                   const float* __restrict__ bs, const float* __restrict__ gs,
                                   const float* __restrict__ bes, float* __restrict__ out) {
    __shared__ float  xs[NN*3];
    __shared__ float  d2s[NN];
    __shared__ __align__(8) float sAx[NN];
    __shared__ __align__(8) float sAy[NN];
    __shared__ __align__(8) float sAz[NN];
    __shared__ __align__(8) float sAr[NN];
    __shared__ __align__(8) float sIs[NN];
    __shared__ __align__(8) float sMs[NN];
    __shared__ int    sel[KNN];
    __shared__ float  rv[8];
    __shared__ int    ri[8];
    int b = blockIdx.x >> 9, i = blockIdx.x & 511;
    int tid = threadIdx.x;
    for (int idx = tid; idx < NN*3; idx += 256) xs[idx] = xyz[b*NN*3 + idx];
    __syncthreads();
    float xi = xs[i*3], yi = xs[i*3+1], zi = xs[i*3+2];
    for (int j = tid; j < NN; j += 256) {
        float a = xi - xs[j*3], bc = yi - xs[j*3+1], c = zi - xs[j*3+2];
        float d2 = a*a + bc*bc + c*c;
        float rd = sqrtf(d2);
        d2s[j] = d2;
        float cf[5] = {a, bc, c, rd, 1.0f};
        float mm = fmaf(a, g_mu[0], fmaf(bc, g_mu[1], fmaf(c, g_mu[2], fmaf(rd, g_mu[3], g_mu[4]))));
        float var = 0.f;
        #pragma unroll
        for (int p = 0; p < 5; p++) {
            float t = 0.f;
            #pragma unroll
            for (int q = 0; q < 5; q++) t = fmaf(g_G[p*5 + q], cf[q], t);
            var = fmaf(cf[p], t, var);
        }
        float is = rsqrtf(var + 1e-5f);
        sAx[j] = a; sAy[j] = bc; sAz[j] = c; sAr[j] = rd;
        sIs[j] = is; sMs[j] = mm * is;
    }
    __syncthreads();
    // --- kNN selection ---
    int lane = tid & 31, warp = tid >> 5;
    for (int it = 0; it < KNN; it++) {
        float v = d2s[tid]; int bi = tid;
        float v2 = d2s[tid + 256];
        if (v2 < v) { v = v2; bi = tid + 256; }
        #pragma unroll
        for (int o = 16; o > 0; o >>= 1) {
            float ov = __shfl_down_sync(0xffffffffu, v, o);
            int   oi = __shfl_down_sync(0xffffffffu, bi, o);
            if (ov < v || (ov == v && oi < bi)) { v = ov; bi = oi; }
        }
        if (lane == 0) { rv[warp] = v; ri[warp] = bi; }
        __syncthreads();
        if (tid == 0) {
            float bv = rv[0]; int bx = ri[0];
            for (int t = 1; t < 8; t++)
                if (rv[t] < bv || (rv[t] == bv && ri[t] < bx)) { bv = rv[t]; bx = ri[t]; }
            sel[it] = bx;
            d2s[bx] = 3.4e38f;
        }
        __syncthreads();
    }
    // --- gather mean over K neighbors ---
    float sg = 0.f;
    #pragma unroll
    for (int k = 0; k < KNN; k++) sg += g_local[(b*NN + sel[k])*DD + tid];
    g_regin[(b*NN + i)*DD + tid] = sg * (1.0f/KNN);
    // --- spatial: packed over j-pairs ---
    float4 wv4 = *(const float4*)(Ws + tid*4);
    float bsd = bs[tid], gd = gs[tid], bed = bes[tid];
    const ull WX = pk2(wv4.x, wv4.x), WY = pk2(wv4.y, wv4.y);
    const ull WZ = pk2(wv4.z, wv4.z), WW = pk2(wv4.w, wv4.w);
    const ull BSD = pk2(bsd, bsd), GD = pk2(gd, gd);
    const ull NGD = pk2(-gd, -gd), BED = pk2(bed, bed);
    const ull ONE2  = pk2(1.0f, 1.0f);
    const ull HALF2 = pk2(0.5f, 0.5f);
    const ull ISQ2  = pk2(0.70710678118654752440f, 0.70710678118654752440f);
    const ull CP    = pk2(0.3275911f, 0.3275911f);
    const ull NA5   = pk2(-1.061405429f, -1.061405429f);
    const ull NA4   = pk2(1.453152027f, 1.453152027f);
    const ull NA3   = pk2(-1.421413741f, -1.421413741f);
    const ull NA2   = pk2(0.284496736f, 0.284496736f);
    const ull NA1   = pk2(-0.254829592f, -0.254829592f);
    const ull NL2E  = pk2(-1.4426950408889634f, -1.4426950408889634f);
    const ull ABSM  = 0x7FFFFFFF7FFFFFFFull;
    const ull SGNM  = 0x8000000080000000ull;
    const ull* pAx = (const ull*)sAx;
    const ull* pAy = (const ull*)sAy;
    const ull* pAz = (const ull*)sAz;
    const ull* pAr = (const ull*)sAr;
    const ull* pIs = (const ull*)sIs;
    const ull* pMs = (const ull*)sMs;
    ull acc2 = 0ull;
    #pragma unroll 2
    for (int j2 = 0; j2 < NN/2; j2++) {
        ull hh = f2fma(pAr[j2], WW, BSD);
        hh = f2fma(pAz[j2], WZ, hh);
        hh = f2fma(pAy[j2], WY, hh);
        hh = f2fma(pAx[j2], WX, hh);
        ull isg = f2mul(pIs[j2], GD);
        ull off = f2fma(pMs[j2], NGD, BED);
        ull t   = f2fma(hh, isg, off);
        // packed gelu
        ull xsp = f2mul(t, ISQ2);
        ull axp = xsp & ABSM;
        ull den = f2fma(axp, CP, ONE2);
        float2 dv = up2(den);
        ull tt = pk2(rcp_fast(dv.x), rcp_fast(dv.y));
        ull p = f2fma(NA5, tt, NA4);
        p = f2fma(p, tt, NA3);
        p = f2fma(p, tt, NA2);
        p = f2fma(p, tt, NA1);
        p = f2mul(p, tt);
        ull m2 = f2mul(xsp, xsp);
        ull ea = f2mul(m2, NL2E);
        float2 ev = up2(ea);
        ull e2 = pk2(ex2_fast(ev.x), ex2_fast(ev.y));
        ull erf2 = f2fma(p, e2, ONE2);          // 1 - |poly|*e  (coeffs pre-negated)
        erf2 = erf2 | (xsp & SGNM);             // copysign (erf2 in [0,1])
        ull phi = f2add(erf2, ONE2);            // 1 + erf
        ull hx = f2mul(t, HALF2);               // 0.5 x
        acc2 = f2fma(hx, phi, acc2);
    }
    float2 av = up2(acc2);
    out[(b*NN + i)*DD + tid] = (av.x + av.y) * (1.0f/NN);
}

// ---------------- K3: gfeat (parallel column-sum via partials + packed matvec) ----------------
__global__ void gfeat_kernel(const float* __restrict__ bg, const float* __restrict__ gg,
                             const float* __restrict__ beg) {
    __shared__ __align__(16) float lm[DD];
    __shared__ float red[16];
    int b = blockIdx.x, tid = threadIdx.x;
    float s = 0.f;
    #pragma unroll 8
    for (int blk = 0; blk < 64; blk++) s += g_part[(b*64 + blk)*DD + tid];
    lm[tid] = s * (1.0f/NN);
    __syncthreads();
    float acc = bg[tid];
    for (int kq = 0; kq < KQD; kq++) {
        float4 l4 = ((const float4*)lm)[kq];
        float4 w = g_Wgp[kq*DD + tid];
        acc = fmaf(l4.x, w.x, acc);
        acc = fmaf(l4.y, w.y, acc);
        acc = fmaf(l4.z, w.z, acc);
        acc = fmaf(l4.w, w.w, acc);
    }
    float sv = acc, s2 = acc*acc;
    #pragma unroll
    for (int o = 16; o > 0; o >>= 1) {
        sv += __shfl_down_sync(0xffffffffu, sv, o);
        s2 += __shfl_down_sync(0xffffffffu, s2, o);
    }
    int w = tid >> 5, l = tid & 31;
    if (l == 0) { red[w] = sv; red[8 + w] = s2; }
    __syncthreads();
    float S = 0.f, S2 = 0.f;
    #pragma unroll
    for (int t = 0; t < 8; t++) { S += red[t]; S2 += red[8 + t]; }
    float m = S * (1.0f/DD);
    float is = rsqrtf(S2 * (1.0f/DD) - m*m + 1e-5f);
    g_gfeat[b*DD + tid] = (acc - m) * is * gg[tid] + beg[tid];
}

// ---------------- K4: region MLP + combined + QKV projection (fused) ----------------
__global__ void region_qkv_kernel(const float* __restrict__ br1, const float* __restrict__ gr1,
                                  const float* __restrict__ ber1, const float* __restrict__ br2,
                                  const float* __restrict__ gr2, const float* __restrict__ ber2,
                                  const float* __restrict__ bin_) {
    __shared__ __align__(16) float in_sh[8][DD];
    __shared__ float h_sh[8][DD];
    __shared__ float stat[8][2];
    int row0 = blockIdx.x * 8;
    int b = row0 >> 9;
    int tid = threadIdx.x;
    for (int idx = tid; idx < 8*DD; idx += 256) {
        int r = idx >> 8, k = idx & 255;
        in_sh[r][k] = g_regin[(row0 + r)*DD + k];
    }
    __syncthreads();
    float acc[8];
    float bbias = br1[tid];
    #pragma unroll
    for (int r = 0; r < 8; r++) acc[r] = bbias;
    for (int kq = 0; kq < KQD; kq++) {
        float4 w = g_Wr1p[kq*DD + tid];
        #pragma unroll
        for (int r = 0; r < 8; r++) {
            float4 iv = ((const float4*)in_sh[r])[kq];
            acc[r] = fmaf(iv.x, w.x, acc[r]);
            acc[r] = fmaf(iv.y, w.y, acc[r]);
            acc[r] = fmaf(iv.z, w.z, acc[r]);
            acc[r] = fmaf(iv.w, w.w, acc[r]);
        }
    }
    #pragma unroll
    for (int r = 0; r < 8; r++) h_sh[r][tid] = acc[r];
    __syncthreads();
    ln_rows8(h_sh, stat);
    float g1 = gr1[tid], b1v = ber1[tid];
    #pragma unroll
    for (int r = 0; r < 8; r++) {
        float t = (h_sh[r][tid] - stat[r][0]) * stat[r][1] * g1 + b1v;
        in_sh[r][tid] = gelu_fast(t);
    }
    __syncthreads();
    bbias = br2[tid];
    #pragma unroll
    for (int r = 0; r < 8; r++) acc[r] = bbias;
    for (int kq = 0; kq < KQD; kq++) {
        float4 w = g_Wr2p[kq*DD + tid];
        #pragma unroll
        for (int r = 0; r < 8; r++) {
            float4 iv = ((const float4*)in_sh[r])[kq];
            acc[r] = fmaf(iv.x, w.x, acc[r]);
            acc[r] = fmaf(iv.y, w.y, acc[r]);
            acc[r] = fmaf(iv.z, w.z, acc[r]);
            acc[r] = fmaf(iv.w, w.w, acc[r]);
        }
    }
    __syncthreads();
    #pragma unroll
    for (int r = 0; r < 8; r++) h_sh[r][tid] = acc[r];
    __syncthreads();
    ln_rows8(h_sh, stat);
    float g2 = gr2[tid], b2v = ber2[tid];
    float gf = g_gfeat[b*DD + tid];
    #pragma unroll
    for (int r = 0; r < 8; r++) {
        int row = row0 + r;
        float t = (h_sh[r][tid] - stat[r][0]) * stat[r][1] * g2 + b2v;
        in_sh[r][tid] = g_local[row*DD + tid] + t + gf;     // combined, stays in smem
    }
    __syncthreads();
    // ---- fused QKV GEMM on combined ----
    float qacc[3][8];
    #pragma unroll
    for (int co = 0; co < 3; co++) {
        float bb = bin_[co*256 + tid];
        #pragma unroll
        for (int r = 0; r < 8; r++) qacc[co][r] = bb;
    }
    for (int kq = 0; kq < KQD; kq++) {
        float4 iv[8];
        #pragma unroll
        for (int r = 0; r < 8; r++) iv[r] = ((const float4*)in_sh[r])[kq];
        #pragma unroll
        for (int co = 0; co < 3; co++) {
            float4 w = g_Winp[kq*QKVD + co*256 + tid];
            #pragma unroll
            for (int r = 0; r < 8; r++) {
                qacc[co][r] = fmaf(iv[r].x, w.x, qacc[co][r]);
                qacc[co][r] = fmaf(iv[r].y, w.y, qacc[co][r]);
                qacc[co][r] = fmaf(iv[r].z, w.z, qacc[co][r]);
                qacc[co][r] = fmaf(iv[r].w, w.w, qacc[co][r]);
            }
        }
    }
    #pragma unroll
    for (int co = 0; co < 3; co++)
        #pragma unroll
        for (int r = 0; r < 8; r++)
            g_qkv[(row0 + r)*QKVD + co*256 + tid] = qacc[co][r];
}

// ---------------- K5: attention split-KV (4 splits of 128 keys) ----------------
__global__ void attn_kernel() {
    __shared__ float Ksh[128][DH];
    __shared__ float Vsh[128][DH];
    int z = blockIdx.z;
    int b = z >> 2, s = z & 3;
    int h = blockIdx.y;
    int qi = blockIdx.x * 64 + threadIdx.x;
    int tid = threadIdx.x;
    const float scale = 0.17677669529663688f;
    float q[DH];
    const float* qrow = g_qkv + (b*NN + qi)*QKVD + h*DH;
    #pragma unroll
    for (int d4 = 0; d4 < DH; d4 += 4) {
        float4 v = *(const float4*)(qrow + d4);
        q[d4] = v.x*scale; q[d4+1] = v.y*scale; q[d4+2] = v.z*scale; q[d4+3] = v.w*scale;
    }
    int jt = s * 128;
    for (int idx = tid; idx < 128*DH; idx += 64) {
        int jj = idx >> 5, dd = idx & 31;
        int base = (b*NN + jt + jj)*QKVD + h*DH + dd;
        Ksh[jj][dd] = g_qkv[base + DD];
        Vsh[jj][dd] = g_qkv[base + 2*DD];
    }
    __syncthreads();
    float m = -1e30f, l = 0.f, o[DH];
    #pragma unroll
    for (int d = 0; d < DH; d++) o[d] = 0.f;
    for (int jj = 0; jj < 128; jj++) {
        float s0 = 0.f, s1 = 0.f, s2 = 0.f, s3 = 0.f;
        #pragma unroll
        for (int d = 0; d < DH; d += 4) {
            s0 = fmaf(q[d],   Ksh[jj][d],   s0);
            s1 = fmaf(q[d+1], Ksh[jj][d+1], s1);
            s2 = fmaf(q[d+2], Ksh[jj][d+2], s2);
            s3 = fmaf(q[d+3], Ksh[jj][d+3], s3);
        }
        float sc = (s0 + s1) + (s2 + s3);
        if (sc > m) {
            float corr = __expf(m - sc);
            l *= corr;
            #pragma unroll
            for (int d = 0; d < DH; d++) o[d] *= corr;
            m = sc;
        }
        float p = __expf(sc - m);
        l += p;
        #pragma unroll
        for (int d = 0; d < DH; d++) o[d] = fmaf(p, Vsh[jj][d], o[d]);
    }
    int pb = ((b*NSPLIT + s)*HH + h)*NN + qi;
    g_pm[pb] = m;
    g_pl[pb] = l;
    float* po = g_po + pb*DH;
    #pragma unroll
    for (int d = 0; d < DH; d++) po[d] = o[d];
}

// ---------------- K6: merge splits + out += o @ Wo.T + bo ----------------
__global__ void oproj_kernel(const float* __restrict__ bo, float* __restrict__ out) {
    __shared__ float esc[8][HH][NSPLIT];
    __shared__ __align__(16) float in_sh[8][DD];
    int row0 = blockIdx.x * 8;
    int b = row0 >> 9;
    int q0 = row0 & 511;
    int tid = threadIdx.x;
    if (tid < 64) {
        int r = tid >> 3, h = tid & 7;
        int q = q0 + r;
        float ms[NSPLIT];
        float mx = -1e30f;
        #pragma unroll
        for (int s = 0; s < NSPLIT; s++) {
            ms[s] = g_pm[((b*NSPLIT + s)*HH + h)*NN + q];
            mx = fmaxf(mx, ms[s]);
        }
        float lsum = 0.f;
        #pragma unroll
        for (int s = 0; s < NSPLIT; s++)
            lsum += g_pl[((b*NSPLIT + s)*HH + h)*NN + q] * __expf(ms[s] - mx);
        float inv = 1.0f / lsum;
        #pragma unroll
        for (int s = 0; s < NSPLIT; s++)
            esc[r][h][s] = __expf(ms[s] - mx) * inv;
    }
    __syncthreads();
    int h = tid >> 5, dh = tid & 31;
    #pragma unroll
    for (int r = 0; r < 8; r++) {
        float o = 0.f;
        #pragma unroll
        for (int s = 0; s < NSPLIT; s++)
            o = fmaf(g_po[(((b*NSPLIT + s)*HH + h)*NN + q0 + r)*DH + dh], esc[r][h][s], o);
        in_sh[r][tid] = o;
    }
    __syncthreads();
    float acc[8];
    float bbias = bo[tid];
    #pragma unroll
    for (int r = 0; r < 8; r++) acc[r] = bbias;
    for (int kq = 0; kq < KQD; kq++) {
        float4 w = g_Wop[kq*DD + tid];
        #pragma unroll
        for (int r = 0; r < 8; r++) {
            float4 iv = ((const float4*)in_sh[r])[kq];
            acc[r] = fmaf(iv.x, w.x, acc[r]);
            acc[r] = fmaf(iv.y, w.y, acc[r]);
            acc[r] = fmaf(iv.z, w.z, acc[r]);
            acc[r] = fmaf(iv.w, w.w, acc[r]);
        }
    }
    #pragma unroll
    for (int r = 0; r < 8; r++)
        out[(row0 + r)*DD + tid] += acc[r];
}

// ---------------- launch ----------------
extern "C" void kernel_launch(void* const* d_in, const int* in_sizes, int n_in,
                              void* d_out, int out_size) {
    const float* x    = (const float*)d_in[0];
    const float* pf   = (const float*)d_in[1];
    const float* xyz  = (const float*)d_in[2];
    const float* W1   = (const float*)d_in[3];
    const float* b1   = (const float*)d_in[4];
    const float* g1   = (const float*)d_in[5];
    const float* be1  = (const float*)d_in[6];
    const float* Wr1  = (const float*)d_in[7];
    const float* br1  = (const float*)d_in[8];
    const float* gr1  = (const float*)d_in[9];
    const float* ber1 = (const float*)d_in[10];
    const float* Wr2  = (const float*)d_in[11];
    const float* br2  = (const float*)d_in[12];
    const float* gr2  = (const float*)d_in[13];
    const float* ber2 = (const float*)d_in[14];
    const float* Wg   = (const float*)d_in[15];
    const float* bg   = (const float*)d_in[16];
    const float* gg   = (const float*)d_in[17];
    const float* beg  = (const float*)d_in[18];
    const float* Win  = (const float*)d_in[19];
    const float* bin_ = (const float*)d_in[20];
    const float* Wo   = (const float*)d_in[21];
    const float* bo   = (const float*)d_in[22];
    const float* Ws   = (const float*)d_in[23];
    const float* bs   = (const float*)d_in[24];
    const float* gs   = (const float*)d_in[25];
    const float* bes  = (const float*)d_in[26];
    float* out = (float*)d_out;

    prep_gram_kernel<<<NPREP + 1, 256>>>(W1, Wr1, Wr2, Win, Wo, Wg, Ws, bs);
    local_encoder_kernel<<<128, 256>>>(x, pf, xyz, b1, g1, be1);
    knn_spatial_kernel<<<BB*NN, 256>>>(xyz, Ws, bs, gs, bes, out);
    gfeat_kernel<<<BB, 256>>>(bg, gg, beg);
    region_qkv_kernel<<<128, 256>>>(br1, gr1, ber1, br2, gr2, ber2, bin_);
    dim3 ag(NN/64, HH, BB*NSPLIT);
    attn_kernel<<<ag, 64>>>();
    oproj_kernel<<<128, 256>>>(bo, out);
}

// round 5
// speedup vs baseline: 2.3536x; 1.0975x over previous
#include <cuda_runtime.h>
#include <math.h>

#define BB 2
#define NN 512
#define CD 64
#define PF 128
#define DD 256
#define KNN 16
#define HH 8
#define DH 32
#define QKVD 768
#define CIN 195
#define KQ1 49      // ceil(195/4)
#define KQD 64      // 256/4
#define NSPLIT 4

typedef unsigned long long ull;

// ---------------- scratch (device globals) ----------------
__device__ float4 g_W1p[KQ1*DD];
__device__ float4 g_Wr1p[KQD*DD];
__device__ float4 g_Wr2p[KQD*DD];
__device__ float4 g_Winp[KQD*QKVD];
__device__ float4 g_Wop[KQD*DD];
__device__ float4 g_Wgp[KQD*DD];
__device__ float g_mu[5];
__device__ float g_G[25];
__device__ __align__(16) float g_local[BB*NN*DD];
__device__ __align__(16) float g_regin[BB*NN*DD];
__device__ __align__(16) float g_qkv[BB*NN*QKVD];
__device__ float g_part[128*DD];
__device__ float g_gfeat[BB*DD];
__device__ float g_pm[BB*NSPLIT*HH*NN];
__device__ float g_pl[BB*NSPLIT*HH*NN];
__device__ __align__(16) float g_po[BB*NSPLIT*HH*NN*DH];

// ---------------- f32x2 packed math ----------------
__device__ __forceinline__ ull f2fma(ull a, ull b, ull c){ ull d; asm("fma.rn.f32x2 %0, %1, %2, %3;" : "=l"(d) : "l"(a), "l"(b), "l"(c)); return d; }
__device__ __forceinline__ ull f2mul(ull a, ull b){ ull d; asm("mul.rn.f32x2 %0, %1, %2;" : "=l"(d) : "l"(a), "l"(b)); return d; }
__device__ __forceinline__ ull pk2(float lo, float hi){ ull r; asm("mov.b64 %0, {%1,%2};" : "=l"(r) : "f"(lo), "f"(hi)); return r; }
__device__ __forceinline__ float2 up2(ull v){ float2 r; asm("mov.b64 {%0,%1}, %2;" : "=f"(r.x), "=f"(r.y) : "l"(v)); return r; }
__device__ __forceinline__ float rcp_fast(float x){ float r; asm("rcp.approx.ftz.f32 %0, %1;" : "=f"(r) : "f"(x)); return r; }
__device__ __forceinline__ float ex2_fast(float x){ float r; asm("ex2.approx.ftz.f32 %0, %1;" : "=f"(r) : "f"(x)); return r; }

// scalar fast exact-GELU (A&S 7.1.26 erf, |eps|<=1.5e-7)
__device__ __forceinline__ float gelu_fast(float x) {
    float xs = x * 0.70710678118654752440f;
    float ax = fabsf(xs);
    float t  = rcp_fast(fmaf(0.3275911f, ax, 1.0f));
    float p  = t * fmaf(t, fmaf(t, fmaf(t, fmaf(t, 1.061405429f, -1.453152027f),
                       1.421413741f), -0.284496736f), 0.254829592f);
    float e  = ex2_fast(-xs * xs * 1.4426950408889634f);
    float erfv = fmaf(-p, e, 1.0f);
    erfv = copysignf(erfv, xs);
    return 0.5f * x * (1.0f + erfv);
}

// ---------------- K0: weight packing + 5x5 Gram ----------------
__device__ __forceinline__ float blockSumAll(float v, float* red) {
    #pragma unroll
    for (int o = 16; o > 0; o >>= 1) v += __shfl_down_sync(0xffffffffu, v, o);
    int w = threadIdx.x >> 5, l = threadIdx.x & 31;
    __syncthreads();
    if (l == 0) red[w] = v;
    __syncthreads();
    return red[0]+red[1]+red[2]+red[3]+red[4]+red[5]+red[6]+red[7];
}

#define NPREP 64
__global__ void prep_gram_kernel(const float* __restrict__ W1, const float* __restrict__ Wr1,
                                 const float* __restrict__ Wr2, const float* __restrict__ Win,
                                 const float* __restrict__ Wo, const float* __restrict__ Wg,
                                 const float* __restrict__ Ws, const float* __restrict__ bs) {
    if (blockIdx.x < NPREP) {
        int i = blockIdx.x * 256 + threadIdx.x;
        int stride = NPREP * 256;
        for (int e = i; e < DD*KQ1; e += stride) {
            int d = e / KQ1, kq = e % KQ1;
            int k = kq * 4;
            float4 v;
            v.x = (k+0 < CIN) ? W1[d*CIN + k+0] : 0.f;
            v.y = (k+1 < CIN) ? W1[d*CIN + k+1] : 0.f;
            v.z = (k+2 < CIN) ? W1[d*CIN + k+2] : 0.f;
            v.w = (k+3 < CIN) ? W1[d*CIN + k+3] : 0.f;
            g_W1p[kq*DD + d] = v;
        }
        for (int e = i; e < DD*KQD; e += stride) {
            int d = e >> 6, kq = e & 63;
            g_Wr1p[kq*DD + d] = ((const float4*)(Wr1 + d*DD))[kq];
            g_Wr2p[kq*DD + d] = ((const float4*)(Wr2 + d*DD))[kq];
            g_Wop [kq*DD + d] = ((const float4*)(Wo  + d*DD))[kq];
            g_Wgp [kq*DD + d] = ((const float4*)(Wg  + d*DD))[kq];
        }
        for (int e = i; e < QKVD*KQD; e += stride) {
            int ch = e >> 6, kq = e & 63;
            g_Winp[kq*QKVD + ch] = ((const float4*)(Win + ch*DD))[kq];
        }
    } else {
        __shared__ float red[8];
        int d = threadIdx.x;
        float4 w4 = *(const float4*)(Ws + d*4);
        float v[5] = {w4.x, w4.y, w4.z, w4.w, bs[d]};
        float mu[5];
        #pragma unroll
        for (int p = 0; p < 5; p++) mu[p] = blockSumAll(v[p], red) * (1.0f/DD);
        #pragma unroll
        for (int p = 0; p < 5; p++) v[p] -= mu[p];
        for (int p = 0; p < 5; p++)
            for (int q = 0; q < 5; q++) {
                float s = blockSumAll(v[p]*v[q], red) * (1.0f/DD);
                if (d == 0) g_G[p*5 + q] = s;
            }
        if (d == 0) { for (int p = 0; p < 5; p++) g_mu[p] = mu[p]; }
    }
}

// ---------------- LN helper (8 rows, 256 threads) ----------------
__device__ __forceinline__ void ln_rows8(float (*h_sh)[DD], float (*stat)[2]) {
    int w = threadIdx.x >> 5, l = threadIdx.x & 31;
    float s = 0.f, s2 = 0.f;
    for (int i = l; i < DD; i += 32) { float v = h_sh[w][i]; s += v; s2 += v*v; }
    #pragma unroll
    for (int o = 16; o > 0; o >>= 1) {
        s  += __shfl_down_sync(0xffffffffu, s,  o);
        s2 += __shfl_down_sync(0xffffffffu, s2, o);
    }
    if (l == 0) {
        float m = s * (1.0f/DD);
        stat[w][0] = m;
        stat[w][1] = rsqrtf(s2 * (1.0f/DD) - m*m + 1e-5f);
    }
    __syncthreads();
}

// ---------------- K1: local encoder (+ column partial sums) ----------------
__global__ void local_encoder_kernel(const float* __restrict__ x, const float* __restrict__ pf,
                                     const float* __restrict__ xyz, const float* __restrict__ b1,
                                     const float* __restrict__ g1, const float* __restrict__ be1) {
    __shared__ __align__(16) float in_sh[8][196];
    __shared__ float h_sh[8][DD];
    __shared__ float stat[8][2];
    int row0 = blockIdx.x * 8;
    int tid = threadIdx.x;
    for (int idx = tid; idx < 8*196; idx += 256) {
        int r = idx / 196, k = idx % 196, row = row0 + r;
        float v;
        if (k < CD)          v = x[row*CD + k];
        else if (k < CD+PF)  v = pf[row*PF + (k - CD)];
        else if (k < CIN)    v = xyz[row*3 + (k - CD - PF)];
        else                 v = 0.f;
        in_sh[r][k] = v;
    }
    __syncthreads();
    float acc[8];
    float bbias = b1[tid];
    #pragma unroll
    for (int r = 0; r < 8; r++) acc[r] = bbias;
    for (int kq = 0; kq < KQ1; kq++) {
        float4 w = g_W1p[kq*DD + tid];
        #pragma unroll
        for (int r = 0; r < 8; r++) {
            float4 iv = ((const float4*)in_sh[r])[kq];
            acc[r] = fmaf(iv.x, w.x, acc[r]);
            acc[r] = fmaf(iv.y, w.y, acc[r]);
            acc[r] = fmaf(iv.z, w.z, acc[r]);
            acc[r] = fmaf(iv.w, w.w, acc[r]);
        }
    }
    #pragma unroll
    for (int r = 0; r < 8; r++) h_sh[r][tid] = acc[r];
    __syncthreads();
    ln_rows8(h_sh, stat);
    float gv = g1[tid], bev = be1[tid];
    float psum = 0.f;
    #pragma unroll
    for (int r = 0; r < 8; r++) {
        float t = (h_sh[r][tid] - stat[r][0]) * stat[r][1] * gv + bev;
        float g = gelu_fast(t);
        psum += g;
        g_local[(row0 + r)*DD + tid] = g;
    }
    g_part[blockIdx.x*DD + tid] = psum;
}

// ---------------- K2: fused gfeat(2 blocks) + kNN + gather + spatial ----------------
__global__ void knn_spatial_kernel(const float* __restrict__ xyz, const float* __restrict__ Ws,
                                   const float* __restrict__ bs, const float* __restrict__ gs,
                                   const float* __restrict__ bes,
                                   const float* __restrict__ bg, const float* __restrict__ gg,
                                   const float* __restrict__ beg,
                                   float* __restrict__ out) {
    __shared__ __align__(16) float xs[NN*3];
    __shared__ float  d2s[NN];
    __shared__ __align__(16) float sPXY[NN*2];   // pair-packed: [j2*4 + {0,1}]=px, [j2*4+{2,3}]=py
    __shared__ __align__(16) float sPZR[NN*2];
    __shared__ __align__(16) float sIM[NN*2];    // pi, pm
    __shared__ float  wV[8*KNN];
    __shared__ int    wI[8*KNN];
    __shared__ int    sel[KNN];
    __shared__ float  sums6[6];
    __shared__ float  red6[8][6];
    int tid = threadIdx.x;
    int lane = tid & 31, warp = tid >> 5;

    if (blockIdx.x < BB) {
        // ================= gfeat path (hidden under spatial blocks) =================
        float* lm = xs;            // alias spatial smem
        float* red = d2s;
        int b = blockIdx.x;
        float s = 0.f;
        #pragma unroll 16
        for (int blk = 0; blk < 64; blk++) s += g_part[(b*64 + blk)*DD + tid];
        lm[tid] = s * (1.0f/NN);
        __syncthreads();
        float acc = bg[tid];
        for (int kq = 0; kq < KQD; kq++) {
            float4 l4 = ((const float4*)lm)[kq];
            float4 w = g_Wgp[kq*DD + tid];
            acc = fmaf(l4.x, w.x, acc);
            acc = fmaf(l4.y, w.y, acc);
            acc = fmaf(l4.z, w.z, acc);
            acc = fmaf(l4.w, w.w, acc);
        }
        float sv = acc, s2 = acc*acc;
        #pragma unroll
        for (int o = 16; o > 0; o >>= 1) {
            sv += __shfl_down_sync(0xffffffffu, sv, o);
            s2 += __shfl_down_sync(0xffffffffu, s2, o);
        }
        if (lane == 0) { red[warp] = sv; red[8 + warp] = s2; }
        __syncthreads();
        float S = 0.f, S2 = 0.f;
        #pragma unroll
        for (int t = 0; t < 8; t++) { S += red[t]; S2 += red[8 + t]; }
        float m = S * (1.0f/DD);
        float is = rsqrtf(S2 * (1.0f/DD) - m*m + 1e-5f);
        g_gfeat[b*DD + tid] = (acc - m) * is * gg[tid] + beg[tid];
        return;
    }

    // ================= kNN + spatial path =================
    int bid = blockIdx.x - BB;
    int b = bid >> 9, i = bid & 511;
    for (int idx = tid; idx < NN*3; idx += 256) xs[idx] = xyz[b*NN*3 + idx];
    __syncthreads();
    float xi = xs[i*3], yi = xs[i*3+1], zi = xs[i*3+2];
    float lsx = 0.f, lsy = 0.f, lsz = 0.f, lsr = 0.f, lsi = 0.f, lsm = 0.f;
    #pragma unroll
    for (int jj = 0; jj < 2; jj++) {
        int j = tid + jj*256;
        float a = xi - xs[j*3], bc = yi - xs[j*3+1], c = zi - xs[j*3+2];
        float d2 = a*a + bc*bc + c*c;
        float rd = sqrtf(d2);
        d2s[j] = d2;
        float cf[5] = {a, bc, c, rd, 1.0f};
        float mm = fmaf(a, g_mu[0], fmaf(bc, g_mu[1], fmaf(c, g_mu[2], fmaf(rd, g_mu[3], g_mu[4]))));
        float var = 0.f;
        #pragma unroll
        for (int p = 0; p < 5; p++) {
            float t = 0.f;
            #pragma unroll
            for (int q = 0; q < 5; q++) t = fmaf(g_G[p*5 + q], cf[q], t);
            var = fmaf(cf[p], t, var);
        }
        float is = rsqrtf(var + 1e-5f);
        float px = is*a, py = is*bc, pz = is*c, pr = is*rd, pm = mm*is;
        int base = (j >> 1)*4 + (j & 1);
        sPXY[base]     = px;  sPXY[base + 2] = py;
        sPZR[base]     = pz;  sPZR[base + 2] = pr;
        sIM[base]      = is;  sIM[base + 2]  = pm;
        lsx += px; lsy += py; lsz += pz; lsr += pr; lsi += is; lsm += pm;
    }
    // block sums of the six per-j quantities (for analytic sum of t)
    #pragma unroll
    for (int o = 16; o > 0; o >>= 1) {
        lsx += __shfl_down_sync(0xffffffffu, lsx, o);
        lsy += __shfl_down_sync(0xffffffffu, lsy, o);
        lsz += __shfl_down_sync(0xffffffffu, lsz, o);
        lsr += __shfl_down_sync(0xffffffffu, lsr, o);
        lsi += __shfl_down_sync(0xffffffffu, lsi, o);
        lsm += __shfl_down_sync(0xffffffffu, lsm, o);
    }
    if (lane == 0) {
        red6[warp][0] = lsx; red6[warp][1] = lsy; red6[warp][2] = lsz;
        red6[warp][3] = lsr; red6[warp][4] = lsi; red6[warp][5] = lsm;
    }
    __syncthreads();
    if (tid < 6) {
        float t = 0.f;
        #pragma unroll
        for (int w = 0; w < 8; w++) t += red6[w][tid];
        sums6[tid] = t;
    }
    // --- kNN: per-warp top-16 (warp w owns j in [w*64, w*64+64)) ---
    {
        int j0 = warp*64 + lane, j1 = j0 + 32;
        float v0 = d2s[j0], v1 = d2s[j1];
        #pragma unroll
        for (int it = 0; it < KNN; it++) {
            float cv; int ci;
            if (v1 < v0) { cv = v1; ci = j1; } else { cv = v0; ci = j0; }
            #pragma unroll
            for (int o = 16; o > 0; o >>= 1) {
                float ov = __shfl_xor_sync(0xffffffffu, cv, o);
                int   oi = __shfl_xor_sync(0xffffffffu, ci, o);
                if (ov < cv || (ov == cv && oi < ci)) { cv = ov; ci = oi; }
            }
            if (lane == 0) { wV[warp*KNN + it] = cv; wI[warp*KNN + it] = ci; }
            if (ci == j0) v0 = 3.4e38f;
            if (ci == j1) v1 = 3.4e38f;
        }
    }
    __syncthreads();
    // --- merge 8x16 candidates (warp 0) ---
    if (warp == 0) {
        float mv[4]; int mi[4];
        #pragma unroll
        for (int q = 0; q < 4; q++) { mv[q] = wV[q*32 + lane]; mi[q] = wI[q*32 + lane]; }
        #pragma unroll
        for (int it = 0; it < KNN; it++) {
            float cv = mv[0]; int ci = mi[0];
            #pragma unroll
            for (int q = 1; q < 4; q++)
                if (mv[q] < cv || (mv[q] == cv && mi[q] < ci)) { cv = mv[q]; ci = mi[q]; }
            #pragma unroll
            for (int o = 16; o > 0; o >>= 1) {
                float ov = __shfl_xor_sync(0xffffffffu, cv, o);
                int   oi = __shfl_xor_sync(0xffffffffu, ci, o);
                if (ov < cv || (ov == cv && oi < ci)) { cv = ov; ci = oi; }
            }
            if (lane == 0) sel[it] = ci;
            #pragma unroll
            for (int q = 0; q < 4; q++) if (mi[q] == ci) mv[q] = 3.4e38f;
        }
    }
    __syncthreads();
    // --- gather mean over K neighbors ---
    float sg = 0.f;
    #pragma unroll
    for (int k = 0; k < KNN; k++) sg += g_local[(b*NN + sel[k])*DD + tid];
    g_regin[(b*NN + i)*DD + tid] = sg * (1.0f/KNN);
    // --- spatial: Sum_j gelu(t_j) = 0.5*Sum t + 0.5*Sum t*erf(t/sqrt2) ---
    float4 wv4 = *(const float4*)(Ws + tid*4);
    float gd = gs[tid], bed = bes[tid];
    float wxp = gd*wv4.x, wyp = gd*wv4.y, wzp = gd*wv4.z, wwp = gd*wv4.w;
    float bsp = gd*bs[tid];
    float sumT = wxp*sums6[0] + wyp*sums6[1] + wzp*sums6[2] + wwp*sums6[3]
               + bsp*sums6[4] - gd*sums6[5] + bed*(float)NN;
    const ull WX = pk2(wxp, wxp), WY = pk2(wyp, wyp);
    const ull WZ = pk2(wzp, wzp), WW = pk2(wwp, wwp);
    const ull BSP = pk2(bsp, bsp), NGD = pk2(-gd, -gd), BED = pk2(bed, bed);
    const ull ONE2  = pk2(1.0f, 1.0f);
    const ull ISQ2  = pk2(0.70710678118654752440f, 0.70710678118654752440f);
    const ull CP    = pk2(0.47047f, 0.47047f);
    const ull C3    = pk2(-0.7478556f, -0.7478556f);
    const ull C2    = pk2(0.0958798f, 0.0958798f);
    const ull C1    = pk2(-0.3480242f, -0.3480242f);
    const ull NL2E  = pk2(-1.4426950408889634f, -1.4426950408889634f);
    const ull ABSM  = 0x7FFFFFFF7FFFFFFFull;
    const ull SGNM  = 0x8000000080000000ull;
    const ulonglong2* pXY = (const ulonglong2*)sPXY;
    const ulonglong2* pZR = (const ulonglong2*)sPZR;
    const ulonglong2* pIM = (const ulonglong2*)sIM;
    ull acc2 = 0ull;
    #pragma unroll 2
    for (int j2 = 0; j2 < NN/2; j2++) {
        ulonglong2 axy = pXY[j2];
        ulonglong2 azr = pZR[j2];
        ulonglong2 aim = pIM[j2];
        ull t = f2fma(NGD, aim.y, BED);
        t = f2fma(BSP, aim.x, t);
        t = f2fma(WW, azr.y, t);
        t = f2fma(WZ, azr.x, t);
        t = f2fma(WY, axy.y, t);
        t = f2fma(WX, axy.x, t);
        // packed erf(t/sqrt2), 3-term A&S 7.1.25
        ull xsp = f2mul(t, ISQ2);
        ull axp = xsp & ABSM;
        ull den = f2fma(axp, CP, ONE2);
        float2 dv = up2(den);
        ull tt = pk2(rcp_fast(dv.x), rcp_fast(dv.y));
        ull p = f2fma(C3, tt, C2);
        p = f2fma(p, tt, C1);
        p = f2mul(p, tt);
        ull m2 = f2mul(xsp, xsp);
        ull ea = f2mul(m2, NL2E);
        float2 ev = up2(ea);
        ull e2 = pk2(ex2_fast(ev.x), ex2_fast(ev.y));
        ull erf2 = f2fma(p, e2, ONE2);
        erf2 = erf2 | (xsp & SGNM);
        acc2 = f2fma(t, erf2, acc2);
    }
    float2 av = up2(acc2);
    out[(b*NN + i)*DD + tid] = 0.5f * (sumT + av.x + av.y) * (1.0f/NN);
}

// ---------------- K3: region MLP + combined + QKV (fused) ----------------
__global__ void region_qkv_kernel(const float* __restrict__ br1, const float* __restrict__ gr1,
                                  const float* __restrict__ ber1, const float* __restrict__ br2,
                                  const float* __restrict__ gr2, const float* __restrict__ ber2,
                                  const float* __restrict__ bin_) {
    __shared__ __align__(16) float in_sh[8][DD];
    __shared__ float h_sh[8][DD];
    __shared__ float stat[8][2];
    int row0 = blockIdx.x * 8;
    int b = row0 >> 9;
    int tid = threadIdx.x;
    for (int idx = tid; idx < 8*DD; idx += 256) {
        int r = idx >> 8, k = idx & 255;
        in_sh[r][k] = g_regin[(row0 + r)*DD + k];
    }
    __syncthreads();
    float acc[8];
    float bbias = br1[tid];
    #pragma unroll
    for (int r = 0; r < 8; r++) acc[r] = bbias;
    for (int kq = 0; kq < KQD; kq++) {
        float4 w = g_Wr1p[kq*DD + tid];
        #pragma unroll
        for (int r = 0; r < 8; r++) {
            float4 iv = ((const float4*)in_sh[r])[kq];
            acc[r] = fmaf(iv.x, w.x, acc[r]);
            acc[r] = fmaf(iv.y, w.y, acc[r]);
            acc[r] = fmaf(iv.z, w.z, acc[r]);
            acc[r] = fmaf(iv.w, w.w, acc[r]);
        }
    }
    #pragma unroll
    for (int r = 0; r < 8; r++) h_sh[r][tid] = acc[r];
    __syncthreads();
    ln_rows8(h_sh, stat);
    float g1 = gr1[tid], b1v = ber1[tid];
    #pragma unroll
    for (int r = 0; r < 8; r++) {
        float t = (h_sh[r][tid] - stat[r][0]) * stat[r][1] * g1 + b1v;
        in_sh[r][tid] = gelu_fast(t);
    }
    __syncthreads();
    bbias = br2[tid];
    #pragma unroll
    for (int r = 0; r < 8; r++) acc[r] = bbias;
    for (int kq = 0; kq < KQD; kq++) {
        float4 w = g_Wr2p[kq*DD + tid];
        #pragma unroll
        for (int r = 0; r < 8; r++) {
            float4 iv = ((const float4*)in_sh[r])[kq];
            acc[r] = fmaf(iv.x, w.x, acc[r]);
            acc[r] = fmaf(iv.y, w.y, acc[r]);
            acc[r] = fmaf(iv.z, w.z, acc[r]);
            acc[r] = fmaf(iv.w, w.w, acc[r]);
        }
    }
    __syncthreads();
    #pragma unroll
    for (int r = 0; r < 8; r++) h_sh[r][tid] = acc[r];
    __syncthreads();
    ln_rows8(h_sh, stat);
    float g2 = gr2[tid], b2v = ber2[tid];
    float gf = g_gfeat[b*DD + tid];
    #pragma unroll
    for (int r = 0; r < 8; r++) {
        int row = row0 + r;
        float t = (h_sh[r][tid] - stat[r][0]) * stat[r][1] * g2 + b2v;
        in_sh[r][tid] = g_local[row*DD + tid] + t + gf;
    }
    __syncthreads();
    float qacc[3][8];
    #pragma unroll
    for (int co = 0; co < 3; co++) {
        float bb = bin_[co*256 + tid];
        #pragma unroll
        for (int r = 0; r < 8; r++) qacc[co][r] = bb;
    }
    for (int kq = 0; kq < KQD; kq++) {
        float4 iv[8];
        #pragma unroll
        for (int r = 0; r < 8; r++) iv[r] = ((const float4*)in_sh[r])[kq];
        #pragma unroll
        for (int co = 0; co < 3; co++) {
            float4 w = g_Winp[kq*QKVD + co*256 + tid];
            #pragma unroll
            for (int r = 0; r < 8; r++) {
                qacc[co][r] = fmaf(iv[r].x, w.x, qacc[co][r]);
                qacc[co][r] = fmaf(iv[r].y, w.y, qacc[co][r]);
                qacc[co][r] = fmaf(iv[r].z, w.z, qacc[co][r]);
                qacc[co][r] = fmaf(iv[r].w, w.w, qacc[co][r]);
            }
        }
    }
    #pragma unroll
    for (int co = 0; co < 3; co++)
        #pragma unroll
        for (int r = 0; r < 8; r++)
            g_qkv[(row0 + r)*QKVD + co*256 + tid] = qacc[co][r];
}

// ---------------- K4: attention split-KV, f32x2-packed ----------------
__global__ void attn_kernel() {
    __shared__ __align__(16) float Ksh[128][DH];
    __shared__ __align__(16) float Vsh[128][DH];
    int z = blockIdx.z;
    int b = z >> 2, s = z & 3;
    int h = blockIdx.y;
    int qi = blockIdx.x * 64 + threadIdx.x;
    int tid = threadIdx.x;
    const float scale = 0.17677669529663688f * 1.4426950408889634f; // 1/sqrt(32)*log2(e)
    ull qp[16];
    const float* qrow = g_qkv + (b*NN + qi)*QKVD + h*DH;
    #pragma unroll
    for (int d4 = 0; d4 < 8; d4++) {
        float4 v = *(const float4*)(qrow + d4*4);
        qp[d4*2]   = pk2(v.x*scale, v.y*scale);
        qp[d4*2+1] = pk2(v.z*scale, v.w*scale);
    }
    int jt = s * 128;
    for (int idx = tid; idx < 128*DH; idx += 64) {
        int jj = idx >> 5, dd = idx & 31;
        int base = (b*NN + jt + jj)*QKVD + h*DH + dd;
        Ksh[jj][dd] = g_qkv[base + DD];
        Vsh[jj][dd] = g_qkv[base + 2*DD];
    }
    __syncthreads();
    float m = -1e30f, l = 0.f;
    ull op[16];
    #pragma unroll
    for (int t = 0; t < 16; t++) op[t] = 0ull;
    for (int jj = 0; jj < 128; jj++) {
        const ulonglong2* kp = (const ulonglong2*)Ksh[jj];
        ull s2a = 0ull, s2b = 0ull;
        #pragma unroll
        for (int t = 0; t < 8; t++) {
            ulonglong2 kv = kp[t];
            s2a = f2fma(qp[t*2],   kv.x, s2a);
            s2b = f2fma(qp[t*2+1], kv.y, s2b);
        }
        float2 sva = up2(s2a), svb = up2(s2b);
        float sc = (sva.x + sva.y) + (svb.x + svb.y);   // score in log2 domain
        if (sc > m) {
            float corr = ex2_fast(m - sc);
            l *= corr;
            ull c2 = pk2(corr, corr);
            #pragma unroll
            for (int t = 0; t < 16; t++) op[t] = f2mul(op[t], c2);
            m = sc;
        }
        float p = ex2_fast(sc - m);
        l += p;
        ull pp = pk2(p, p);
        const ulonglong2* vp = (const ulonglong2*)Vsh[jj];
        #pragma unroll
        for (int t = 0; t < 8; t++) {
            ulonglong2 vv = vp[t];
            op[t*2]   = f2fma(pp, vv.x, op[t*2]);
            op[t*2+1] = f2fma(pp, vv.y, op[t*2+1]);
        }
    }
    int pb = ((b*NSPLIT + s)*HH + h)*NN + qi;
    g_pm[pb] = m;
    g_pl[pb] = l;
    float* po = g_po + pb*DH;
    #pragma unroll
    for (int t = 0; t < 16; t++) {
        float2 ov = up2(op[t]);
        po[t*2]   = ov.x;
        po[t*2+1] = ov.y;
    }
}

// ---------------- K5: merge splits + out += o @ Wo.T + bo ----------------
__global__ void oproj_kernel(const float* __restrict__ bo, float* __restrict__ out) {
    __shared__ float esc[8][HH][NSPLIT];
    __shared__ __align__(16) float in_sh[8][DD];
    int row0 = blockIdx.x * 8;
    int b = row0 >> 9;
    int q0 = row0 & 511;
    int tid = threadIdx.x;
    if (tid < 64) {
        int r = tid >> 3, h = tid & 7;
        int q = q0 + r;
        float ms[NSPLIT];
        float mx = -1e30f;
        #pragma unroll
        for (int s = 0; s < NSPLIT; s++) {
            ms[s] = g_pm[((b*NSPLIT + s)*HH + h)*NN + q];
            mx = fmaxf(mx, ms[s]);
        }
        float lsum = 0.f;
        #pragma unroll
        for (int s = 0; s < NSPLIT; s++)
            lsum += g_pl[((b*NSPLIT + s)*HH + h)*NN + q] * ex2_fast(ms[s] - mx);  // log2-domain m
        float inv = 1.0f / lsum;
        #pragma unroll
        for (int s = 0; s < NSPLIT; s++)
            esc[r][h][s] = ex2_fast(ms[s] - mx) * inv;
    }
    __syncthreads();
    int h = tid >> 5, dh = tid & 31;
    #pragma unroll
    for (int r = 0; r < 8; r++) {
        float o = 0.f;
        #pragma unroll
        for (int s = 0; s < NSPLIT; s++)
            o = fmaf(g_po[(((b*NSPLIT + s)*HH + h)*NN + q0 + r)*DH + dh], esc[r][h][s], o);
        in_sh[r][tid] = o;
    }
    __syncthreads();
    float acc[8];
    float bbias = bo[tid];
    #pragma unroll
    for (int r = 0; r < 8; r++) acc[r] = bbias;
    for (int kq = 0; kq < KQD; kq++) {
        float4 w = g_Wop[kq*DD + tid];
        #pragma unroll
        for (int r = 0; r < 8; r++) {
            float4 iv = ((const float4*)in_sh[r])[kq];
            acc[r] = fmaf(iv.x, w.x, acc[r]);
            acc[r] = fmaf(iv.y, w.y, acc[r]);
            acc[r] = fmaf(iv.z, w.z, acc[r]);
            acc[r] = fmaf(iv.w, w.w, acc[r]);
        }
    }
    #pragma unroll
    for (int r = 0; r < 8; r++)
        out[(row0 + r)*DD + tid] += acc[r];
}

// ---------------- launch ----------------
extern "C" void kernel_launch(void* const* d_in, const int* in_sizes, int n_in,
                              void* d_out, int out_size) {
    const float* x    = (const float*)d_in[0];
    const float* pf   = (const float*)d_in[1];
    const float* xyz  = (const float*)d_in[2];
    const float* W1   = (const float*)d_in[3];
    const float* b1   = (const float*)d_in[4];
    const float* g1   = (const float*)d_in[5];
    const float* be1  = (const float*)d_in[6];
    const float* Wr1  = (const float*)d_in[7];
    const float* br1  = (const float*)d_in[8];
    const float* gr1  = (const float*)d_in[9];
    const float* ber1 = (const float*)d_in[10];
    const float* Wr2  = (const float*)d_in[11];
    const float* br2  = (const float*)d_in[12];
    const float* gr2  = (const float*)d_in[13];
    const float* ber2 = (const float*)d_in[14];
    const float* Wg   = (const float*)d_in[15];
    const float* bg   = (const float*)d_in[16];
    const float* gg   = (const float*)d_in[17];
    const float* beg  = (const float*)d_in[18];
    const float* Win  = (const float*)d_in[19];
    const float* bin_ = (const float*)d_in[20];
    const float* Wo   = (const float*)d_in[21];
    const float* bo   = (const float*)d_in[22];
    const float* Ws   = (const float*)d_in[23];
    const float* bs   = (const float*)d_in[24];
    const float* gs   = (const float*)d_in[25];
    const float* bes  = (const float*)d_in[26];
    float* out = (float*)d_out;

    prep_gram_kernel<<<NPREP + 1, 256>>>(W1, Wr1, Wr2, Win, Wo, Wg, Ws, bs);
    local_encoder_kernel<<<128, 256>>>(x, pf, xyz, b1, g1, be1);
    knn_spatial_kernel<<<BB*NN + BB, 256>>>(xyz, Ws, bs, gs, bes, bg, gg, beg, out);
    region_qkv_kernel<<<128, 256>>>(br1, gr1, ber1, br2, gr2, ber2, bin_);
    dim3 ag(NN/64, HH, BB*NSPLIT);
    attn_kernel<<<ag, 64>>>();
    oproj_kernel<<<128, 256>>>(bo, out);
}